// round 14
// baseline (speedup 1.0000x reference)
#include <cuda_runtime.h>
#include <cuda_fp16.h>
#include <math.h>
#include <stdint.h>

// ---------------- problem constants ----------------
#define B_   2
#define S_   2048
#define H_   1024
#define NH_  16
#define HD_  64
#define T_   (B_*S_)      // 4096 tokens
#define FFN_ 4096
#define ROT_ 16

// ---------------- static scratch ----------------
__device__ float  d_big[T_*FFN_];
__device__ float  d_x1 [T_*H_];
__device__ __half d_xnh [T_*H_];
__device__ __half d_bigh[T_*FFN_];
__device__ __half d_oh  [T_*H_];
__device__ __half d_qh  [T_*H_];
__device__ __half d_kh  [T_*H_];
__device__ __half d_vh  [T_*H_];
__device__ __half d_vth [T_*H_];
__device__ __half d_qkh[H_*H_];
__device__ __half d_kkh[H_*H_];
__device__ __half d_vkh[H_*H_];
__device__ __half d_pkh[H_*H_];
__device__ __half d_fkh[FFN_*H_];
__device__ __half d_qvh[H_*H_];
__device__ __half d_kvh[H_*H_];
__device__ __half d_vvh[H_*H_];
__device__ __half d_pvh[H_*H_];
__device__ __half d_fvh[H_*FFN_];

// ---------------- helpers ----------------
__device__ __forceinline__ float gelu_exact(float x) {
    return 0.5f * x * (1.0f + erff(x * 0.7071067811865475f));
}
__device__ __forceinline__ int hperm(int u) { return 2 * (u & 3) + (u >> 2); }

__device__ __forceinline__ uint32_t h2u(float a, float b) {
    __half2 h = __floats2half2_rn(a, b);
    return *(uint32_t*)&h;
}
__device__ __forceinline__ float2 u2f(uint32_t u) {
    __half2 h = *(__half2*)&u;
    return __half22float2(h);
}
__device__ __forceinline__ void pack16(const float* f, uint4& lo, uint4& hi) {
    lo.x = h2u(f[0], f[1]);   lo.y = h2u(f[8], f[9]);
    lo.z = h2u(f[2], f[3]);   lo.w = h2u(f[10], f[11]);
    hi.x = h2u(f[4], f[5]);   hi.y = h2u(f[12], f[13]);
    hi.z = h2u(f[6], f[7]);   hi.w = h2u(f[14], f[15]);
}
__device__ __forceinline__ void unpack16(const uint4 lo, const uint4 hi, float* f) {
    float2 t;
    t = u2f(lo.x); f[0]  = t.x; f[1]  = t.y;
    t = u2f(lo.y); f[8]  = t.x; f[9]  = t.y;
    t = u2f(lo.z); f[2]  = t.x; f[3]  = t.y;
    t = u2f(lo.w); f[10] = t.x; f[11] = t.y;
    t = u2f(hi.x); f[4]  = t.x; f[5]  = t.y;
    t = u2f(hi.y); f[12] = t.x; f[13] = t.y;
    t = u2f(hi.z); f[6]  = t.x; f[7]  = t.y;
    t = u2f(hi.w); f[14] = t.x; f[15] = t.y;
}

__device__ __forceinline__ void mma_f16(float* d, const uint32_t* a, const uint32_t* b) {
    asm volatile(
        "mma.sync.aligned.m16n8k16.row.col.f32.f16.f16.f32 "
        "{%0,%1,%2,%3}, {%4,%5,%6,%7}, {%8,%9}, {%0,%1,%2,%3};\n"
        : "+f"(d[0]), "+f"(d[1]), "+f"(d[2]), "+f"(d[3])
        : "r"(a[0]), "r"(a[1]), "r"(a[2]), "r"(a[3]), "r"(b[0]), "r"(b[1]));
}
__device__ __forceinline__ void cp_async16(uint32_t smem_addr, const void* gptr) {
    asm volatile("cp.async.cg.shared.global [%0], [%1], 16;\n" :: "r"(smem_addr), "l"(gptr));
}
#define CP_COMMIT() asm volatile("cp.async.commit_group;\n" ::: "memory")
#define CP_WAIT(n)  asm volatile("cp.async.wait_group %0;\n" :: "n"(n) : "memory")

__device__ __forceinline__ float block_reduce_sum(float v, float* sh) {
    int lane = threadIdx.x & 31, wid = threadIdx.x >> 5;
    #pragma unroll
    for (int o = 16; o > 0; o >>= 1) v += __shfl_down_sync(0xffffffffu, v, o);
    if (lane == 0) sh[wid] = v;
    __syncthreads();
    float r = (threadIdx.x < (blockDim.x >> 5)) ? sh[threadIdx.x] : 0.0f;
    if (wid == 0) {
        #pragma unroll
        for (int o = 4; o > 0; o >>= 1) r += __shfl_down_sync(0xffffffffu, r, o);
        if (lane == 0) sh[0] = r;
    }
    __syncthreads();
    r = sh[0];
    __syncthreads();
    return r;
}

// ---------------- batched param structs ----------------
struct Prep5 {
    const float* in[5];
    __half* out[5];
    int n16[5];
    int R[5];
};
struct Gemm3 {
    const __half* A[3];
    const __half* B[3];
    void* C[3];
    int emode[3];
};
struct Rn3 {
    const float* in[3];
    __half* out[3];
};

// ---------------- batched weight prep ----------------
__global__ void round_perm_kernel(Prep5 p) {
    int z = blockIdx.y;
    int i = blockIdx.x * blockDim.x + threadIdx.x;
    if (i >= p.n16[z]) return;
    const float* src = p.in[z] + (size_t)i * 16;
    float f[16];
    #pragma unroll
    for (int j = 0; j < 16; j += 4) {
        float4 v = *(const float4*)(src + j);
        f[j] = v.x; f[j+1] = v.y; f[j+2] = v.z; f[j+3] = v.w;
    }
    uint4 lo, hi;
    pack16(f, lo, hi);
    uint4* o = (uint4*)(p.out[z] + (size_t)i * 16);
    o[0] = lo; o[1] = hi;
}

__global__ void transpose_kernel(Prep5 p) {
    __shared__ float t[32][33];
    int z = blockIdx.z;
    int R = p.R[z];
    if (blockIdx.y * 32 >= R) return;
    const float* in = p.in[z];
    __half* out = p.out[z];
    int x  = blockIdx.x * 32 + threadIdx.x;
    int y0 = blockIdx.y * 32;
    #pragma unroll
    for (int i = threadIdx.y; i < 32; i += 8)
        t[i][threadIdx.x] = in[(size_t)(y0 + i) * H_ + x];
    __syncthreads();
    int xo = blockIdx.y * 32 + threadIdx.x;
    int r  = xo & 15;
    int xo_p = (xo & ~15) | (2 * hperm(r >> 1) + (r & 1));
    int yo0 = blockIdx.x * 32;
    #pragma unroll
    for (int i = threadIdx.y; i < 32; i += 8)
        out[(size_t)(yo0 + i) * R + xo_p] = __float2half(t[threadIdx.x][i]);
}

// ---------------- V^T per head ----------------
__global__ void vt_kernel(const __half* __restrict__ V, __half* __restrict__ VT) {
    __shared__ __half t[32][34];
    int bh   = blockIdx.z;
    int b    = bh >> 4, h = bh & 15;
    int tok0 = blockIdx.x * 32;
    int dim0 = blockIdx.y * 32;
    int tx = threadIdx.x, ty = threadIdx.y;
    #pragma unroll
    for (int i = ty; i < 32; i += 8)
        t[i][tx] = V[(size_t)(b * S_ + tok0 + i) * H_ + h * HD_ + dim0 + tx];
    __syncthreads();
    int tok = tok0 + tx;
    int tokp = (tok & ~15) | (2 * hperm((tok & 15) >> 1) + (tok & 1));
    #pragma unroll
    for (int i = ty; i < 32; i += 8)
        VT[(size_t)(bh * HD_ + dim0 + i) * S_ + tokp] = t[tx][i];
}

// ---------------- LayerNorm ----------------
__global__ void ln_kernel(const float* __restrict__ x, const float* __restrict__ w,
                          const float* __restrict__ b, __half* __restrict__ y) {
    __shared__ float sh[32];
    int row = blockIdx.x;
    int tid = threadIdx.x;
    const float* xr = x + (size_t)row * H_ + tid * 16;
    float f[16];
    float s = 0.0f, sq = 0.0f;
    #pragma unroll
    for (int j = 0; j < 16; j += 4) {
        float4 v = *(const float4*)(xr + j);
        f[j] = v.x; f[j+1] = v.y; f[j+2] = v.z; f[j+3] = v.w;
        s  += v.x + v.y + v.z + v.w;
        sq += v.x*v.x + v.y*v.y + v.z*v.z + v.w*v.w;
    }
    float S  = block_reduce_sum(s,  sh);
    float SQ = block_reduce_sum(sq, sh);
    float mu  = S * (1.0f / H_);
    float var = SQ * (1.0f / H_) - mu * mu;
    float inv = rsqrtf(var + 1e-5f);
    const float* wr = w + tid * 16;
    const float* br = b + tid * 16;
    #pragma unroll
    for (int j = 0; j < 16; j++)
        f[j] = (f[j] - mu) * inv * wr[j] + br[j];
    uint4 lo, hi;
    pack16(f, lo, hi);
    uint4* o = (uint4*)(y + (size_t)row * H_ + tid * 16);
    o[0] = lo; o[1] = hi;
}

// ---------------- gelu + L2-rownorm core ----------------
__device__ __forceinline__ void rownorm_row(const float* ar, __half* orow, int cols, float* sh) {
    int tid = threadIdx.x;
    const float* src = ar + tid * 16;
    float g[16];
    float s = 0.0f;
    #pragma unroll
    for (int j = 0; j < 16; j += 4) {
        float4 v = *(const float4*)(src + j);
        g[j]   = gelu_exact(v.x); g[j+1] = gelu_exact(v.y);
        g[j+2] = gelu_exact(v.z); g[j+3] = gelu_exact(v.w);
        s += g[j]*g[j] + g[j+1]*g[j+1] + g[j+2]*g[j+2] + g[j+3]*g[j+3];
    }
    float tot = block_reduce_sum(s, sh);
    float sc = sqrtf((float)cols) * rsqrtf(tot);
    #pragma unroll
    for (int j = 0; j < 16; j++) g[j] *= sc;
    uint4 lo, hi;
    pack16(g, lo, hi);
    uint4* o = (uint4*)(orow + tid * 16);
    o[0] = lo; o[1] = hi;
}

__global__ void rownorm3_kernel(Rn3 p) {
    __shared__ float sh[32];
    int z = blockIdx.y, row = blockIdx.x;
    rownorm_row(p.in[z] + (size_t)row * H_, p.out[z] + (size_t)row * H_, H_, sh);
}
template <int NT>
__global__ void rownorm_kernel(const float* __restrict__ in, __half* __restrict__ out, int cols) {
    __shared__ float sh[32];
    int row = blockIdx.x;
    rownorm_row(in + (size_t)row * cols, out + (size_t)row * cols, cols, sh);
}

// ---------------- FP16 GEMM core (NT, 128x128x32 k-tile, cp.async 3-stage) ----------------
// Row = 32 halves = 8 uint2 data + 4 pad = 12 uint2 (96B).
#define HSTR 12
#define HTSZ (128 * HSTR)

__device__ __forceinline__ void hgemm_body(
    const __half* A, const __half* Bm, const float* Res, void* Cv,
    int M, int N, int K, float alpha, int emode, uint2* sh2)
{
    uint2* As = sh2;              // [3][HTSZ]
    uint2* Bs = sh2 + 3 * HTSZ;   // [3][HTSZ]

    const int bx = blockIdx.x, by = blockIdx.y;
    const int tid = threadIdx.x;
    const int lane = tid & 31, w = tid >> 5;
    const int wm = w & 3, wn = w >> 2;          // 4x2 warps; warp tile 32m x 64n
    const int lr = lane >> 2, lc = lane & 3;

    float acc[2][8][4];
    #pragma unroll
    for (int i = 0; i < 2; i++)
        #pragma unroll
        for (int j = 0; j < 8; j++)
            #pragma unroll
            for (int t = 0; t < 4; t++) acc[i][j][t] = 0.0f;

    const int iters = K >> 5;                   // 32-k tiles
    const int r_ld = tid >> 1;                  // 0..127
    const int c2   = (tid & 1) * 2;             // chunk 0/2

    auto load_tile = [&](int t, int buf) {
        int k0 = t << 5;
        const __half* srcA = A + (size_t)(by * 128 + r_ld) * K + k0 + c2 * 8;
        uint32_t dA = (uint32_t)__cvta_generic_to_shared(As + buf * HTSZ + r_ld * HSTR + c2 * 2);
        cp_async16(dA,      srcA);
        cp_async16(dA + 16, srcA + 8);
        const __half* srcB = Bm + (size_t)(bx * 128 + r_ld) * K + k0 + c2 * 8;
        uint32_t dB = (uint32_t)__cvta_generic_to_shared(Bs + buf * HTSZ + r_ld * HSTR + c2 * 2);
        cp_async16(dB,      srcB);
        cp_async16(dB + 16, srcB + 8);
    };

    // prologue: 2 tiles in flight
    load_tile(0, 0);
    CP_COMMIT();
    if (iters > 1) {
        load_tile(1, 1);
        CP_COMMIT();
    }

    int buf = 0;
    for (int t = 0; t < iters; t++) {
        if (t + 1 < iters) CP_WAIT(1); else CP_WAIT(0);
        __syncthreads();    // tile t visible; all warps done with buffer being overwritten next
        if (t + 2 < iters) {
            int nb = buf + 2; if (nb >= 3) nb -= 3;
            load_tile(t + 2, nb);
            CP_COMMIT();
        }
        const uint2* Ab = As + buf * HTSZ;
        const uint2* Bb = Bs + buf * HTSZ;
        #pragma unroll
        for (int ks = 0; ks < 2; ks++) {
            uint32_t afr[2][4];
            #pragma unroll
            for (int mt = 0; mt < 2; mt++) {
                const uint2* ap = Ab + (wm * 32 + mt * 16 + lr) * HSTR + ks * 4 + lc;
                uint2 p0 = ap[0];
                uint2 p1 = ap[8 * HSTR];
                afr[mt][0] = p0.x; afr[mt][1] = p1.x;
                afr[mt][2] = p0.y; afr[mt][3] = p1.y;
            }
            #pragma unroll
            for (int nt = 0; nt < 8; nt++) {
                const uint2* bp = Bb + (wn * 64 + nt * 8 + lr) * HSTR + ks * 4 + lc;
                uint2 bb = bp[0];
                uint32_t bfr[2] = {bb.x, bb.y};
                mma_f16(acc[0][nt], afr[0], bfr);
                mma_f16(acc[1][nt], afr[1], bfr);
            }
        }
        buf++; if (buf == 3) buf = 0;
    }

    #pragma unroll
    for (int mt = 0; mt < 2; mt++) {
        int r0 = by * 128 + wm * 32 + mt * 16 + lr;
        #pragma unroll
        for (int nt = 0; nt < 8; nt++) {
            int c = bx * 128 + wn * 64 + nt * 8 + 2 * lc;
            float a0 = acc[mt][nt][0] * alpha, a1 = acc[mt][nt][1] * alpha;
            float a2 = acc[mt][nt][2] * alpha, a3 = acc[mt][nt][3] * alpha;
            if (emode == 0) {
                float* C = (float*)Cv;
                float2 lo = {a0, a1}, hi = {a2, a3};
                if (Res) {
                    float2 rlo = *(const float2*)(Res + (size_t)r0 * N + c);
                    float2 rhi = *(const float2*)(Res + (size_t)(r0 + 8) * N + c);
                    lo.x += rlo.x; lo.y += rlo.y; hi.x += rhi.x; hi.y += rhi.y;
                }
                *(float2*)(C + (size_t)r0 * N + c)       = lo;
                *(float2*)(C + (size_t)(r0 + 8) * N + c) = hi;
            } else if (emode == 1) {
                __half* C = (__half*)Cv;
                int hoff = (c & ~15) + 4 * lc + 2 * (nt & 1);
                ((uint32_t*)(C + (size_t)r0 * N))[hoff >> 1]       = h2u(a0, a1);
                ((uint32_t*)(C + (size_t)(r0 + 8) * N))[hoff >> 1] = h2u(a2, a3);
            } else {
                __half* C = (__half*)Cv;
                ((uint32_t*)(C + (size_t)r0 * N))[c >> 1]       = h2u(a0, a1);
                ((uint32_t*)(C + (size_t)(r0 + 8) * N))[c >> 1] = h2u(a2, a3);
            }
        }
    }
}

template <int EMODE>
__global__ void __launch_bounds__(256) hgemm_kernel(
    const __half* __restrict__ A, const __half* __restrict__ Bm,
    const float* __restrict__ Res, void* __restrict__ Cv,
    int M, int N, int K, float alpha)
{
    extern __shared__ uint2 sh2[];
    hgemm_body(A, Bm, Res, Cv, M, N, K, alpha, EMODE, sh2);
}

__global__ void __launch_bounds__(256) hgemm3_kernel(
    Gemm3 g, int M, int N, int K, float alpha)
{
    extern __shared__ uint2 sh2[];
    int z = blockIdx.z;
    hgemm_body(g.A[z], g.B[z], nullptr, g.C[z], M, N, K, alpha, g.emode[z], sh2);
}

// ---------------- RoPE on half k-permuted Q,K ----------------
__global__ void rope_kernel(__half* __restrict__ q, __half* __restrict__ k) {
    int idx = blockIdx.x * blockDim.x + threadIdx.x;
    if (idx >= T_ * NH_) return;
    int h  = idx & (NH_ - 1);
    int bs = idx >> 4;
    int s  = bs & (S_ - 1);
    __half* qp = q + (size_t)bs * H_ + h * HD_;
    __half* kp = k + (size_t)bs * H_ + h * HD_;
    uint4 qlo = *(uint4*)qp, qhi = *(uint4*)(qp + 8);
    uint4 klo = *(uint4*)kp, khi = *(uint4*)(kp + 8);
    float qv[16], kv[16];
    unpack16(qlo, qhi, qv);
    unpack16(klo, khi, kv);
    #pragma unroll
    for (int i = 0; i < ROT_ / 2; i++) {
        double invf = pow(10000.0, -(double)(2 * i) / (double)ROT_);
        double ang = (double)s * invf;
        float c  = (float)cos(ang);
        float sn = (float)sin(ang);
        float q0 = qv[i], q1 = qv[i + 8];
        qv[i]     = q0 * c - q1 * sn;
        qv[i + 8] = q1 * c + q0 * sn;
        float k0 = kv[i], k1 = kv[i + 8];
        kv[i]     = k0 * c - k1 * sn;
        kv[i + 8] = k1 * c + k0 * sn;
    }
    pack16(qv, qlo, qhi);
    pack16(kv, klo, khi);
    *(uint4*)qp = qlo; *(uint4*)(qp + 8) = qhi;
    *(uint4*)kp = klo; *(uint4*)(kp + 8) = khi;
}

// ---------------- fused causal attention (fp16 mma, 128-q tiles, 8 warps) ----------------
#define VSTR 20
#define ATSZ (64 * VSTR)
#define QTSZ (128 * VSTR)

__global__ void __launch_bounds__(256, 2) attn_kernel(
    const __half* __restrict__ Q, const __half* __restrict__ K,
    const __half* __restrict__ VT, __half* __restrict__ O)
{
    extern __shared__ uint2 sm2[];
    uint2* Qs = sm2;
    uint2* Ks = Qs + QTSZ;
    uint2* Vs = Ks + 2 * ATSZ;
    uint2* Ss = Vs + 2 * ATSZ;

    const int qt  = blockIdx.x;
    const int bh  = blockIdx.y;
    const int b   = bh >> 4, h = bh & 15;
    const int tid = threadIdx.x;
    const int lane = tid & 31, w = tid >> 5;
    const int lr = lane >> 2, lc = lane & 3;
    const size_t baseQK = (size_t)(b * S_) * H_ + h * HD_;
    const size_t baseVT = (size_t)(bh * HD_) * S_;

    #pragma unroll
    for (int it = 0; it < 4; it++) {
        int c = tid + it * 256;
        int r = c >> 3, off = c & 7;
        const __half* src = Q + baseQK + (size_t)(qt * 128 + r) * H_ + off * 8;
        uint32_t dst = (uint32_t)__cvta_generic_to_shared(Qs + r * VSTR + off * 2);
        cp_async16(dst, src);
    }
    #pragma unroll
    for (int it = 0; it < 2; it++) {
        int c = tid + it * 256;
        int r = c >> 3, off = c & 7;
        const __half* srck = K + baseQK + (size_t)r * H_ + off * 8;
        uint32_t dk = (uint32_t)__cvta_generic_to_shared(Ks + r * VSTR + off * 2);
        cp_async16(dk, srck);
        const __half* srcv = VT + baseVT + (size_t)r * S_ + off * 8;
        uint32_t dv = (uint32_t)__cvta_generic_to_shared(Vs + r * VSTR + off * 2);
        cp_async16(dv, srcv);
    }
    CP_COMMIT();

    float oacc[8][4];
    #pragma unroll
    for (int i = 0; i < 8; i++)
        #pragma unroll
        for (int j = 0; j < 4; j++) oacc[i][j] = 0.0f;
    float n2lo = 0.0f, n2hi = 0.0f;

    const int jmax = 2 * qt + 1;
    int buf = 0;
    for (int j = 0; j <= jmax; j++) {
        CP_WAIT(0);
        __syncthreads();

        if (j < jmax) {
            #pragma unroll
            for (int it = 0; it < 2; it++) {
                int c = tid + it * 256;
                int r = c >> 3, off = c & 7;
                const __half* srck = K + baseQK + (size_t)((j + 1) * 64 + r) * H_ + off * 8;
                uint32_t dk = (uint32_t)__cvta_generic_to_shared(Ks + (buf ^ 1) * ATSZ + r * VSTR + off * 2);
                cp_async16(dk, srck);
                const __half* srcv = VT + baseVT + (size_t)r * S_ + (j + 1) * 64 + off * 8;
                uint32_t dv = (uint32_t)__cvta_generic_to_shared(Vs + (buf ^ 1) * ATSZ + r * VSTR + off * 2);
                cp_async16(dv, srcv);
            }
            CP_COMMIT();
        }

        const uint2* Kb = Ks + buf * ATSZ;
        const uint2* Vb = Vs + buf * ATSZ;

        float sacc[8][4];
        #pragma unroll
        for (int i = 0; i < 8; i++)
            #pragma unroll
            for (int jj = 0; jj < 4; jj++) sacc[i][jj] = 0.0f;
        #pragma unroll
        for (int ks = 0; ks < 4; ks++) {
            const uint2* ap = Qs + (w * 16 + lr) * VSTR + ks * 4 + lc;
            uint2 p0 = ap[0];
            uint2 p1 = ap[8 * VSTR];
            uint32_t a[4] = {p0.x, p1.x, p0.y, p1.y};
            #pragma unroll
            for (int nt = 0; nt < 8; nt++) {
                uint2 bb = Kb[(nt * 8 + lr) * VSTR + ks * 4 + lc];
                uint32_t bfr[2] = {bb.x, bb.y};
                mma_f16(sacc[nt], a, bfr);
            }
        }

        int q0 = qt * 128 + w * 16 + lr;
        uint32_t* Ss32 = (uint32_t*)Ss;
        #pragma unroll
        for (int nt = 0; nt < 8; nt++) {
            int k0c = j * 64 + nt * 8 + 2 * lc;
            float g0 = (k0c     <= q0)     ? gelu_exact(sacc[nt][0] * 0.125f) : 0.0f;
            float g1 = (k0c + 1 <= q0)     ? gelu_exact(sacc[nt][1] * 0.125f) : 0.0f;
            float g2 = (k0c     <= q0 + 8) ? gelu_exact(sacc[nt][2] * 0.125f) : 0.0f;
            float g3 = (k0c + 1 <= q0 + 8) ? gelu_exact(sacc[nt][3] * 0.125f) : 0.0f;
            n2lo += g0 * g0 + g1 * g1;
            n2hi += g2 * g2 + g3 * g3;
            int slot = (nt >> 1) * 8 + 2 * lc + (nt & 1);
            Ss32[(w * 16 + lr)     * (2 * VSTR) + slot] = h2u(g0, g1);
            Ss32[(w * 16 + lr + 8) * (2 * VSTR) + slot] = h2u(g2, g3);
        }
        __syncwarp();

        #pragma unroll
        for (int ks = 0; ks < 4; ks++) {
            const uint2* ap = Ss + (w * 16 + lr) * VSTR + ks * 4 + lc;
            uint2 p0 = ap[0];
            uint2 p1 = ap[8 * VSTR];
            uint32_t a[4] = {p0.x, p1.x, p0.y, p1.y};
            #pragma unroll
            for (int nt = 0; nt < 8; nt++) {
                uint2 bb = Vb[(nt * 8 + lr) * VSTR + ks * 4 + lc];
                uint32_t bfr[2] = {bb.x, bb.y};
                mma_f16(oacc[nt], a, bfr);
            }
        }
        buf ^= 1;
    }

    n2lo += __shfl_xor_sync(0xffffffffu, n2lo, 1);
    n2lo += __shfl_xor_sync(0xffffffffu, n2lo, 2);
    n2hi += __shfl_xor_sync(0xffffffffu, n2hi, 1);
    n2hi += __shfl_xor_sync(0xffffffffu, n2hi, 2);

    const float sqS = 45.25483399593904f;
    float sclo = sqS * rsqrtf(n2lo);
    float schi = sqS * rsqrtf(n2hi);

    int r0 = qt * 128 + w * 16 + lr;
    #pragma unroll
    for (int nt = 0; nt < 8; nt++) {
        int c = nt * 8 + 2 * lc;
        int pp = (c & ~15) | (2 * hperm((c & 15) >> 1));
        __half* o0 = O + baseQK + (size_t)r0 * H_;
        __half* o1 = O + baseQK + (size_t)(r0 + 8) * H_;
        ((uint32_t*)o0)[pp >> 1] = h2u(oacc[nt][0] * sclo, oacc[nt][1] * sclo);
        ((uint32_t*)o1)[pp >> 1] = h2u(oacc[nt][2] * schi, oacc[nt][3] * schi);
    }
}

// ---------------- launch ----------------
extern "C" void kernel_launch(void* const* d_in, const int* in_sizes, int n_in,
                              void* d_out, int out_size) {
    const float* x        = (const float*)d_in[0];
    const float* ln1_w    = (const float*)d_in[1];
    const float* ln1_b    = (const float*)d_in[2];
    const float* ln2_w    = (const float*)d_in[3];
    const float* ln2_b    = (const float*)d_in[4];
    const float* q_key    = (const float*)d_in[5];
    const float* q_val    = (const float*)d_in[6];
    const float* k_key    = (const float*)d_in[7];
    const float* k_val    = (const float*)d_in[8];
    const float* v_key    = (const float*)d_in[9];
    const float* v_val    = (const float*)d_in[10];
    const float* proj_key = (const float*)d_in[11];
    const float* proj_val = (const float*)d_in[12];
    const float* ffn_key  = (const float*)d_in[13];
    const float* ffn_val  = (const float*)d_in[14];
    float* out = (float*)d_out;

    float *p_big, *p_x1;
    __half *p_xnh, *p_bigh, *p_oh, *p_qh, *p_kh, *p_vh, *p_vth;
    __half *p_qkh, *p_kkh, *p_vkh, *p_pkh, *p_fkh;
    __half *p_qvh, *p_kvh, *p_vvh, *p_pvh, *p_fvh;
    cudaGetSymbolAddress((void**)&p_big,  d_big);
    cudaGetSymbolAddress((void**)&p_x1,   d_x1);
    cudaGetSymbolAddress((void**)&p_xnh,  d_xnh);
    cudaGetSymbolAddress((void**)&p_bigh, d_bigh);
    cudaGetSymbolAddress((void**)&p_oh,   d_oh);
    cudaGetSymbolAddress((void**)&p_qh,   d_qh);
    cudaGetSymbolAddress((void**)&p_kh,   d_kh);
    cudaGetSymbolAddress((void**)&p_vh,   d_vh);
    cudaGetSymbolAddress((void**)&p_vth,  d_vth);
    cudaGetSymbolAddress((void**)&p_qkh,  d_qkh);
    cudaGetSymbolAddress((void**)&p_kkh,  d_kkh);
    cudaGetSymbolAddress((void**)&p_vkh,  d_vkh);
    cudaGetSymbolAddress((void**)&p_pkh,  d_pkh);
    cudaGetSymbolAddress((void**)&p_fkh,  d_fkh);
    cudaGetSymbolAddress((void**)&p_qvh,  d_qvh);
    cudaGetSymbolAddress((void**)&p_kvh,  d_kvh);
    cudaGetSymbolAddress((void**)&p_vvh,  d_vvh);
    cudaGetSymbolAddress((void**)&p_pvh,  d_pvh);
    cudaGetSymbolAddress((void**)&p_fvh,  d_fvh);

    float*  big_q = p_big;
    float*  big_k = p_big + (size_t)T_ * H_;
    float*  big_v = p_big + (size_t)2 * T_ * H_;
    __half* bgh_q = p_bigh;
    __half* bgh_k = p_bigh + (size_t)T_ * H_;
    __half* bgh_v = p_bigh + (size_t)2 * T_ * H_;

    const float sqrtH = 32.0f;
    dim3 g_small(H_ / 128, T_ / 128);
    dim3 g_small3(H_ / 128, T_ / 128, 3);
    dim3 g_ffn1(FFN_ / 128, T_ / 128);
    dim3 tthr(32, 8);

    const int smem_g = 6 * HTSZ * 8;           // 73728 bytes (3 stages x (A+B) 32-k tiles)
    cudaFuncSetAttribute(hgemm_kernel<0>, cudaFuncAttributeMaxDynamicSharedMemorySize, smem_g);
    cudaFuncSetAttribute(hgemm3_kernel,   cudaFuncAttributeMaxDynamicSharedMemorySize, smem_g);
    const int smem_a = (2 * QTSZ + 4 * ATSZ) * 8;    // 81920 bytes
    cudaFuncSetAttribute(attn_kernel, cudaFuncAttributeMaxDynamicSharedMemorySize, smem_a);

    const int n16_hh = H_ * H_ / 16, n16_fh = FFN_ * H_ / 16;

    // ---- batched weight prep ----
    {
        Prep5 rp;
        rp.in[0] = q_key;  rp.out[0] = p_qkh; rp.n16[0] = n16_hh; rp.R[0] = H_;
        rp.in[1] = k_key;  rp.out[1] = p_kkh; rp.n16[1] = n16_hh; rp.R[1] = H_;
        rp.in[2] = v_key;  rp.out[2] = p_vkh; rp.n16[2] = n16_hh; rp.R[2] = H_;
        rp.in[3] = proj_key; rp.out[3] = p_pkh; rp.n16[3] = n16_hh; rp.R[3] = H_;
        rp.in[4] = ffn_key;  rp.out[4] = p_fkh; rp.n16[4] = n16_fh; rp.R[4] = FFN_;
        dim3 g((n16_fh + 255) / 256, 5);
        round_perm_kernel<<<g, 256>>>(rp);

        Prep5 tp;
        tp.in[0] = q_val;    tp.out[0] = p_qvh; tp.n16[0] = 0; tp.R[0] = H_;
        tp.in[1] = k_val;    tp.out[1] = p_kvh; tp.n16[1] = 0; tp.R[1] = H_;
        tp.in[2] = v_val;    tp.out[2] = p_vvh; tp.n16[2] = 0; tp.R[2] = H_;
        tp.in[3] = proj_val; tp.out[3] = p_pvh; tp.n16[3] = 0; tp.R[3] = H_;
        tp.in[4] = ffn_val;  tp.out[4] = p_fvh; tp.n16[4] = 0; tp.R[4] = FFN_;
        dim3 gt(H_ / 32, FFN_ / 32, 5);
        transpose_kernel<<<gt, tthr>>>(tp);
    }

    ln_kernel<<<T_, 64>>>(x, ln1_w, ln1_b, p_xnh);

    // ---- qkv pattention (batched) ----
    {
        Gemm3 g1;
        g1.A[0] = p_xnh; g1.B[0] = p_qkh; g1.C[0] = big_q; g1.emode[0] = 0;
        g1.A[1] = p_xnh; g1.B[1] = p_kkh; g1.C[1] = big_k; g1.emode[1] = 0;
        g1.A[2] = p_xnh; g1.B[2] = p_vkh; g1.C[2] = big_v; g1.emode[2] = 0;
        hgemm3_kernel<<<g_small3, 256, smem_g>>>(g1, T_, H_, H_, sqrtH);

        Rn3 rn;
        rn.in[0] = big_q; rn.out[0] = bgh_q;
        rn.in[1] = big_k; rn.out[1] = bgh_k;
        rn.in[2] = big_v; rn.out[2] = bgh_v;
        dim3 gr(T_, 3);
        rownorm3_kernel<<<gr, 64>>>(rn);

        Gemm3 g2;
        g2.A[0] = bgh_q; g2.B[0] = p_qvh; g2.C[0] = p_qh; g2.emode[0] = 1;
        g2.A[1] = bgh_k; g2.B[1] = p_kvh; g2.C[1] = p_kh; g2.emode[1] = 1;
        g2.A[2] = bgh_v; g2.B[2] = p_vvh; g2.C[2] = p_vh; g2.emode[2] = 2;
        hgemm3_kernel<<<g_small3, 256, smem_g>>>(g2, T_, H_, H_, 1.0f);
    }

    rope_kernel<<<(T_ * NH_) / 256, 256>>>(p_qh, p_kh);
    {
        dim3 vtg(S_ / 32, HD_ / 32, B_ * NH_);
        vt_kernel<<<vtg, tthr>>>(p_vh, p_vth);
    }

    {
        dim3 grid(S_ / 128, B_ * NH_);
        attn_kernel<<<grid, 256, smem_a>>>(p_qh, p_kh, p_vth, p_oh);
    }

    // proj pattention + fused residual
    hgemm_kernel<0><<<g_small, 256, smem_g>>>(p_oh, p_pkh, nullptr, big_q, T_, H_, H_, sqrtH);
    rownorm_kernel<64><<<T_, 64>>>(big_q, bgh_q, H_);
    hgemm_kernel<0><<<g_small, 256, smem_g>>>(bgh_q, p_pvh, x, p_x1, T_, H_, H_, 1.0f);

    // ffn pattention + fused residual
    ln_kernel<<<T_, 64>>>(p_x1, ln2_w, ln2_b, p_xnh);
    hgemm_kernel<0><<<g_ffn1, 256, smem_g>>>(p_xnh, p_fkh, nullptr, p_big, T_, FFN_, H_, sqrtH);
    rownorm_kernel<256><<<T_, 256>>>(p_big, p_bigh, FFN_);
    hgemm_kernel<0><<<g_small, 256, smem_g>>>(p_bigh, p_fvh, p_x1, out, T_, H_, FFN_, 1.0f);
}

// round 15
// speedup vs baseline: 1.2183x; 1.2183x over previous
#include <cuda_runtime.h>
#include <cuda_fp16.h>
#include <math.h>
#include <stdint.h>

// ---------------- problem constants ----------------
#define B_   2
#define S_   2048
#define H_   1024
#define NH_  16
#define HD_  64
#define T_   (B_*S_)      // 4096 tokens
#define FFN_ 4096
#define ROT_ 16

// ---------------- static scratch ----------------
__device__ float  d_big[T_*FFN_];
__device__ float  d_x1 [T_*H_];
__device__ __half d_xnh [T_*H_];
__device__ __half d_bigh[T_*FFN_];
__device__ __half d_oh  [T_*H_];
__device__ __half d_qh  [T_*H_];
__device__ __half d_kh  [T_*H_];
__device__ __half d_vh  [T_*H_];
__device__ __half d_vth [T_*H_];
__device__ __half d_qkh[H_*H_];
__device__ __half d_kkh[H_*H_];
__device__ __half d_vkh[H_*H_];
__device__ __half d_pkh[H_*H_];
__device__ __half d_fkh[FFN_*H_];
__device__ __half d_qvh[H_*H_];
__device__ __half d_kvh[H_*H_];
__device__ __half d_vvh[H_*H_];
__device__ __half d_pvh[H_*H_];
__device__ __half d_fvh[H_*FFN_];

// ---------------- helpers ----------------
__device__ __forceinline__ float gelu_exact(float x) {
    return 0.5f * x * (1.0f + erff(x * 0.7071067811865475f));
}
__device__ __forceinline__ int hperm(int u) { return 2 * (u & 3) + (u >> 2); }

__device__ __forceinline__ uint32_t h2u(float a, float b) {
    __half2 h = __floats2half2_rn(a, b);
    return *(uint32_t*)&h;
}
__device__ __forceinline__ float2 u2f(uint32_t u) {
    __half2 h = *(__half2*)&u;
    return __half22float2(h);
}
__device__ __forceinline__ void pack16(const float* f, uint4& lo, uint4& hi) {
    lo.x = h2u(f[0], f[1]);   lo.y = h2u(f[8], f[9]);
    lo.z = h2u(f[2], f[3]);   lo.w = h2u(f[10], f[11]);
    hi.x = h2u(f[4], f[5]);   hi.y = h2u(f[12], f[13]);
    hi.z = h2u(f[6], f[7]);   hi.w = h2u(f[14], f[15]);
}
__device__ __forceinline__ void unpack16(const uint4 lo, const uint4 hi, float* f) {
    float2 t;
    t = u2f(lo.x); f[0]  = t.x; f[1]  = t.y;
    t = u2f(lo.y); f[8]  = t.x; f[9]  = t.y;
    t = u2f(lo.z); f[2]  = t.x; f[3]  = t.y;
    t = u2f(lo.w); f[10] = t.x; f[11] = t.y;
    t = u2f(hi.x); f[4]  = t.x; f[5]  = t.y;
    t = u2f(hi.y); f[12] = t.x; f[13] = t.y;
    t = u2f(hi.z); f[6]  = t.x; f[7]  = t.y;
    t = u2f(hi.w); f[14] = t.x; f[15] = t.y;
}

__device__ __forceinline__ void mma_f16(float* d, const uint32_t* a, const uint32_t* b) {
    asm volatile(
        "mma.sync.aligned.m16n8k16.row.col.f32.f16.f16.f32 "
        "{%0,%1,%2,%3}, {%4,%5,%6,%7}, {%8,%9}, {%0,%1,%2,%3};\n"
        : "+f"(d[0]), "+f"(d[1]), "+f"(d[2]), "+f"(d[3])
        : "r"(a[0]), "r"(a[1]), "r"(a[2]), "r"(a[3]), "r"(b[0]), "r"(b[1]));
}
__device__ __forceinline__ void cp_async16(uint32_t smem_addr, const void* gptr) {
    asm volatile("cp.async.cg.shared.global [%0], [%1], 16;\n" :: "r"(smem_addr), "l"(gptr));
}
#define CP_COMMIT() asm volatile("cp.async.commit_group;\n" ::: "memory")
#define CP_WAIT(n)  asm volatile("cp.async.wait_group %0;\n" :: "n"(n) : "memory")

__device__ __forceinline__ float block_reduce_sum(float v, float* sh) {
    int lane = threadIdx.x & 31, wid = threadIdx.x >> 5;
    #pragma unroll
    for (int o = 16; o > 0; o >>= 1) v += __shfl_down_sync(0xffffffffu, v, o);
    if (lane == 0) sh[wid] = v;
    __syncthreads();
    float r = (threadIdx.x < (blockDim.x >> 5)) ? sh[threadIdx.x] : 0.0f;
    if (wid == 0) {
        #pragma unroll
        for (int o = 4; o > 0; o >>= 1) r += __shfl_down_sync(0xffffffffu, r, o);
        if (lane == 0) sh[0] = r;
    }
    __syncthreads();
    r = sh[0];
    __syncthreads();
    return r;
}

// ---------------- batched param structs ----------------
struct Prep5 {
    const float* in[5];
    __half* out[5];
    int n16[5];
    int R[5];
};
struct Gemm3 {
    const __half* A[3];
    const __half* B[3];
    void* C[3];
    int emode[3];
};
struct Rn3 {
    const float* in[3];
    __half* out[3];
};

// ---------------- batched weight prep ----------------
__global__ void round_perm_kernel(Prep5 p) {
    int z = blockIdx.y;
    int i = blockIdx.x * blockDim.x + threadIdx.x;
    if (i >= p.n16[z]) return;
    const float* src = p.in[z] + (size_t)i * 16;
    float f[16];
    #pragma unroll
    for (int j = 0; j < 16; j += 4) {
        float4 v = *(const float4*)(src + j);
        f[j] = v.x; f[j+1] = v.y; f[j+2] = v.z; f[j+3] = v.w;
    }
    uint4 lo, hi;
    pack16(f, lo, hi);
    uint4* o = (uint4*)(p.out[z] + (size_t)i * 16);
    o[0] = lo; o[1] = hi;
}

__global__ void transpose_kernel(Prep5 p) {
    __shared__ float t[32][33];
    int z = blockIdx.z;
    int R = p.R[z];
    if (blockIdx.y * 32 >= R) return;
    const float* in = p.in[z];
    __half* out = p.out[z];
    int x  = blockIdx.x * 32 + threadIdx.x;
    int y0 = blockIdx.y * 32;
    #pragma unroll
    for (int i = threadIdx.y; i < 32; i += 8)
        t[i][threadIdx.x] = in[(size_t)(y0 + i) * H_ + x];
    __syncthreads();
    int xo = blockIdx.y * 32 + threadIdx.x;
    int r  = xo & 15;
    int xo_p = (xo & ~15) | (2 * hperm(r >> 1) + (r & 1));
    int yo0 = blockIdx.x * 32;
    #pragma unroll
    for (int i = threadIdx.y; i < 32; i += 8)
        out[(size_t)(yo0 + i) * R + xo_p] = __float2half(t[threadIdx.x][i]);
}

// ---------------- V^T per head ----------------
__global__ void vt_kernel(const __half* __restrict__ V, __half* __restrict__ VT) {
    __shared__ __half t[32][34];
    int bh   = blockIdx.z;
    int b    = bh >> 4, h = bh & 15;
    int tok0 = blockIdx.x * 32;
    int dim0 = blockIdx.y * 32;
    int tx = threadIdx.x, ty = threadIdx.y;
    #pragma unroll
    for (int i = ty; i < 32; i += 8)
        t[i][tx] = V[(size_t)(b * S_ + tok0 + i) * H_ + h * HD_ + dim0 + tx];
    __syncthreads();
    int tok = tok0 + tx;
    int tokp = (tok & ~15) | (2 * hperm((tok & 15) >> 1) + (tok & 1));
    #pragma unroll
    for (int i = ty; i < 32; i += 8)
        VT[(size_t)(bh * HD_ + dim0 + i) * S_ + tokp] = t[tx][i];
}

// ---------------- LayerNorm ----------------
__global__ void ln_kernel(const float* __restrict__ x, const float* __restrict__ w,
                          const float* __restrict__ b, __half* __restrict__ y) {
    __shared__ float sh[32];
    int row = blockIdx.x;
    int tid = threadIdx.x;
    const float* xr = x + (size_t)row * H_ + tid * 16;
    float f[16];
    float s = 0.0f, sq = 0.0f;
    #pragma unroll
    for (int j = 0; j < 16; j += 4) {
        float4 v = *(const float4*)(xr + j);
        f[j] = v.x; f[j+1] = v.y; f[j+2] = v.z; f[j+3] = v.w;
        s  += v.x + v.y + v.z + v.w;
        sq += v.x*v.x + v.y*v.y + v.z*v.z + v.w*v.w;
    }
    float S  = block_reduce_sum(s,  sh);
    float SQ = block_reduce_sum(sq, sh);
    float mu  = S * (1.0f / H_);
    float var = SQ * (1.0f / H_) - mu * mu;
    float inv = rsqrtf(var + 1e-5f);
    const float* wr = w + tid * 16;
    const float* br = b + tid * 16;
    #pragma unroll
    for (int j = 0; j < 16; j++)
        f[j] = (f[j] - mu) * inv * wr[j] + br[j];
    uint4 lo, hi;
    pack16(f, lo, hi);
    uint4* o = (uint4*)(y + (size_t)row * H_ + tid * 16);
    o[0] = lo; o[1] = hi;
}

// ---------------- gelu + L2-rownorm core ----------------
__device__ __forceinline__ void rownorm_row(const float* ar, __half* orow, int cols, float* sh) {
    int tid = threadIdx.x;
    const float* src = ar + tid * 16;
    float g[16];
    float s = 0.0f;
    #pragma unroll
    for (int j = 0; j < 16; j += 4) {
        float4 v = *(const float4*)(src + j);
        g[j]   = gelu_exact(v.x); g[j+1] = gelu_exact(v.y);
        g[j+2] = gelu_exact(v.z); g[j+3] = gelu_exact(v.w);
        s += g[j]*g[j] + g[j+1]*g[j+1] + g[j+2]*g[j+2] + g[j+3]*g[j+3];
    }
    float tot = block_reduce_sum(s, sh);
    float sc = sqrtf((float)cols) * rsqrtf(tot);
    #pragma unroll
    for (int j = 0; j < 16; j++) g[j] *= sc;
    uint4 lo, hi;
    pack16(g, lo, hi);
    uint4* o = (uint4*)(orow + tid * 16);
    o[0] = lo; o[1] = hi;
}

__global__ void rownorm3_kernel(Rn3 p) {
    __shared__ float sh[32];
    int z = blockIdx.y, row = blockIdx.x;
    rownorm_row(p.in[z] + (size_t)row * H_, p.out[z] + (size_t)row * H_, H_, sh);
}
template <int NT>
__global__ void rownorm_kernel(const float* __restrict__ in, __half* __restrict__ out, int cols) {
    __shared__ float sh[32];
    int row = blockIdx.x;
    rownorm_row(in + (size_t)row * cols, out + (size_t)row * cols, cols, sh);
}

// ---------------- FP16 GEMM core (NT, 128x128x64 k-tile, cp.async 2-stage, 1 sync/iter) --------
// Row = 64 halves = 16 uint2 data + 4 pad = 20 uint2 (160B).
#define HSTR 20
#define HTSZ (128 * HSTR)

__device__ __forceinline__ void hgemm_body(
    const __half* A, const __half* Bm, const float* Res, void* Cv,
    int M, int N, int K, float alpha, int emode, uint2* sh2)
{
    uint2* As = sh2;              // [2][HTSZ]
    uint2* Bs = sh2 + 2 * HTSZ;   // [2][HTSZ]

    const int bx = blockIdx.x, by = blockIdx.y;
    const int tid = threadIdx.x;
    const int lane = tid & 31, w = tid >> 5;
    const int wm = w & 3, wn = w >> 2;          // 4x2 warps; warp tile 32m x 64n
    const int lr = lane >> 2, lc = lane & 3;

    float acc[2][8][4];
    #pragma unroll
    for (int i = 0; i < 2; i++)
        #pragma unroll
        for (int j = 0; j < 8; j++)
            #pragma unroll
            for (int t = 0; t < 4; t++) acc[i][j][t] = 0.0f;

    const int iters = K >> 6;                   // 64-k tiles

    auto load_tile = [&](int t, int buf) {
        int k0 = t << 6;
        #pragma unroll
        for (int it = 0; it < 4; it++) {
            int slot = tid + it * 256;
            int r = slot >> 3, off = slot & 7;
            const __half* srcA = A + (size_t)(by * 128 + r) * K + k0 + off * 8;
            uint32_t dA = (uint32_t)__cvta_generic_to_shared(As + buf * HTSZ + r * HSTR + off * 2);
            cp_async16(dA, srcA);
            const __half* srcB = Bm + (size_t)(bx * 128 + r) * K + k0 + off * 8;
            uint32_t dB = (uint32_t)__cvta_generic_to_shared(Bs + buf * HTSZ + r * HSTR + off * 2);
            cp_async16(dB, srcB);
        }
    };

    load_tile(0, 0);
    CP_COMMIT();

    // loop-invariant fragment row bases (per-buffer), constant offsets inside
    const int aoff = (wm * 32 + lr) * HSTR + lc;
    const int boff = (wn * 64 + lr) * HSTR + lc;

    int buf = 0;
    for (int t = 0; t < iters; t++) {
        CP_WAIT(0);
        __syncthreads();
        if (t + 1 < iters) {
            load_tile(t + 1, buf ^ 1);
            CP_COMMIT();
        }
        const uint2* aRow = As + buf * HTSZ + aoff;
        const uint2* bRow = Bs + buf * HTSZ + boff;
        #pragma unroll
        for (int ks = 0; ks < 4; ks++) {
            uint32_t afr[2][4];
            #pragma unroll
            for (int mt = 0; mt < 2; mt++) {
                uint2 p0 = aRow[mt * 16 * HSTR + ks * 4];           // constant offsets
                uint2 p1 = aRow[(mt * 16 + 8) * HSTR + ks * 4];
                afr[mt][0] = p0.x; afr[mt][1] = p1.x;
                afr[mt][2] = p0.y; afr[mt][3] = p1.y;
            }
            #pragma unroll
            for (int nt = 0; nt < 8; nt++) {
                uint2 bb = bRow[nt * 8 * HSTR + ks * 4];            // constant offset
                uint32_t bfr[2] = {bb.x, bb.y};
                mma_f16(acc[0][nt], afr[0], bfr);
                mma_f16(acc[1][nt], afr[1], bfr);
            }
        }
        buf ^= 1;
    }

    #pragma unroll
    for (int mt = 0; mt < 2; mt++) {
        int r0 = by * 128 + wm * 32 + mt * 16 + lr;
        #pragma unroll
        for (int nt = 0; nt < 8; nt++) {
            int c = bx * 128 + wn * 64 + nt * 8 + 2 * lc;
            float a0 = acc[mt][nt][0] * alpha, a1 = acc[mt][nt][1] * alpha;
            float a2 = acc[mt][nt][2] * alpha, a3 = acc[mt][nt][3] * alpha;
            if (emode == 0) {
                float* C = (float*)Cv;
                float2 lo = {a0, a1}, hi = {a2, a3};
                if (Res) {
                    float2 rlo = *(const float2*)(Res + (size_t)r0 * N + c);
                    float2 rhi = *(const float2*)(Res + (size_t)(r0 + 8) * N + c);
                    lo.x += rlo.x; lo.y += rlo.y; hi.x += rhi.x; hi.y += rhi.y;
                }
                *(float2*)(C + (size_t)r0 * N + c)       = lo;
                *(float2*)(C + (size_t)(r0 + 8) * N + c) = hi;
            } else if (emode == 1) {
                __half* C = (__half*)Cv;
                int hoff = (c & ~15) + 4 * lc + 2 * (nt & 1);
                ((uint32_t*)(C + (size_t)r0 * N))[hoff >> 1]       = h2u(a0, a1);
                ((uint32_t*)(C + (size_t)(r0 + 8) * N))[hoff >> 1] = h2u(a2, a3);
            } else {
                __half* C = (__half*)Cv;
                ((uint32_t*)(C + (size_t)r0 * N))[c >> 1]       = h2u(a0, a1);
                ((uint32_t*)(C + (size_t)(r0 + 8) * N))[c >> 1] = h2u(a2, a3);
            }
        }
    }
}

template <int EMODE>
__global__ void __launch_bounds__(256, 2) hgemm_kernel(
    const __half* __restrict__ A, const __half* __restrict__ Bm,
    const float* __restrict__ Res, void* __restrict__ Cv,
    int M, int N, int K, float alpha)
{
    extern __shared__ uint2 sh2[];
    hgemm_body(A, Bm, Res, Cv, M, N, K, alpha, EMODE, sh2);
}

__global__ void __launch_bounds__(256, 2) hgemm3_kernel(
    Gemm3 g, int M, int N, int K, float alpha)
{
    extern __shared__ uint2 sh2[];
    int z = blockIdx.z;
    hgemm_body(g.A[z], g.B[z], nullptr, g.C[z], M, N, K, alpha, g.emode[z], sh2);
}

// ---------------- RoPE on half k-permuted Q,K ----------------
__global__ void rope_kernel(__half* __restrict__ q, __half* __restrict__ k) {
    int idx = blockIdx.x * blockDim.x + threadIdx.x;
    if (idx >= T_ * NH_) return;
    int h  = idx & (NH_ - 1);
    int bs = idx >> 4;
    int s  = bs & (S_ - 1);
    __half* qp = q + (size_t)bs * H_ + h * HD_;
    __half* kp = k + (size_t)bs * H_ + h * HD_;
    uint4 qlo = *(uint4*)qp, qhi = *(uint4*)(qp + 8);
    uint4 klo = *(uint4*)kp, khi = *(uint4*)(kp + 8);
    float qv[16], kv[16];
    unpack16(qlo, qhi, qv);
    unpack16(klo, khi, kv);
    #pragma unroll
    for (int i = 0; i < ROT_ / 2; i++) {
        double invf = pow(10000.0, -(double)(2 * i) / (double)ROT_);
        double ang = (double)s * invf;
        float c  = (float)cos(ang);
        float sn = (float)sin(ang);
        float q0 = qv[i], q1 = qv[i + 8];
        qv[i]     = q0 * c - q1 * sn;
        qv[i + 8] = q1 * c + q0 * sn;
        float k0 = kv[i], k1 = kv[i + 8];
        kv[i]     = k0 * c - k1 * sn;
        kv[i + 8] = k1 * c + k0 * sn;
    }
    pack16(qv, qlo, qhi);
    pack16(kv, klo, khi);
    *(uint4*)qp = qlo; *(uint4*)(qp + 8) = qhi;
    *(uint4*)kp = klo; *(uint4*)(kp + 8) = khi;
}

// ---------------- fused causal attention (fp16 mma, 128-q tiles, 8 warps) ----------------
#define VSTR 20
#define ATSZ (64 * VSTR)
#define QTSZ (128 * VSTR)

__global__ void __launch_bounds__(256, 2) attn_kernel(
    const __half* __restrict__ Q, const __half* __restrict__ K,
    const __half* __restrict__ VT, __half* __restrict__ O)
{
    extern __shared__ uint2 sm2[];
    uint2* Qs = sm2;
    uint2* Ks = Qs + QTSZ;
    uint2* Vs = Ks + 2 * ATSZ;
    uint2* Ss = Vs + 2 * ATSZ;

    const int qt  = blockIdx.x;
    const int bh  = blockIdx.y;
    const int b   = bh >> 4, h = bh & 15;
    const int tid = threadIdx.x;
    const int lane = tid & 31, w = tid >> 5;
    const int lr = lane >> 2, lc = lane & 3;
    const size_t baseQK = (size_t)(b * S_) * H_ + h * HD_;
    const size_t baseVT = (size_t)(bh * HD_) * S_;

    #pragma unroll
    for (int it = 0; it < 4; it++) {
        int c = tid + it * 256;
        int r = c >> 3, off = c & 7;
        const __half* src = Q + baseQK + (size_t)(qt * 128 + r) * H_ + off * 8;
        uint32_t dst = (uint32_t)__cvta_generic_to_shared(Qs + r * VSTR + off * 2);
        cp_async16(dst, src);
    }
    #pragma unroll
    for (int it = 0; it < 2; it++) {
        int c = tid + it * 256;
        int r = c >> 3, off = c & 7;
        const __half* srck = K + baseQK + (size_t)r * H_ + off * 8;
        uint32_t dk = (uint32_t)__cvta_generic_to_shared(Ks + r * VSTR + off * 2);
        cp_async16(dk, srck);
        const __half* srcv = VT + baseVT + (size_t)r * S_ + off * 8;
        uint32_t dv = (uint32_t)__cvta_generic_to_shared(Vs + r * VSTR + off * 2);
        cp_async16(dv, srcv);
    }
    CP_COMMIT();

    float oacc[8][4];
    #pragma unroll
    for (int i = 0; i < 8; i++)
        #pragma unroll
        for (int j = 0; j < 4; j++) oacc[i][j] = 0.0f;
    float n2lo = 0.0f, n2hi = 0.0f;

    const int jmax = 2 * qt + 1;
    int buf = 0;
    for (int j = 0; j <= jmax; j++) {
        CP_WAIT(0);
        __syncthreads();

        if (j < jmax) {
            #pragma unroll
            for (int it = 0; it < 2; it++) {
                int c = tid + it * 256;
                int r = c >> 3, off = c & 7;
                const __half* srck = K + baseQK + (size_t)((j + 1) * 64 + r) * H_ + off * 8;
                uint32_t dk = (uint32_t)__cvta_generic_to_shared(Ks + (buf ^ 1) * ATSZ + r * VSTR + off * 2);
                cp_async16(dk, srck);
                const __half* srcv = VT + baseVT + (size_t)r * S_ + (j + 1) * 64 + off * 8;
                uint32_t dv = (uint32_t)__cvta_generic_to_shared(Vs + (buf ^ 1) * ATSZ + r * VSTR + off * 2);
                cp_async16(dv, srcv);
            }
            CP_COMMIT();
        }

        const uint2* Kb = Ks + buf * ATSZ;
        const uint2* Vb = Vs + buf * ATSZ;

        float sacc[8][4];
        #pragma unroll
        for (int i = 0; i < 8; i++)
            #pragma unroll
            for (int jj = 0; jj < 4; jj++) sacc[i][jj] = 0.0f;
        #pragma unroll
        for (int ks = 0; ks < 4; ks++) {
            const uint2* ap = Qs + (w * 16 + lr) * VSTR + ks * 4 + lc;
            uint2 p0 = ap[0];
            uint2 p1 = ap[8 * VSTR];
            uint32_t a[4] = {p0.x, p1.x, p0.y, p1.y};
            #pragma unroll
            for (int nt = 0; nt < 8; nt++) {
                uint2 bb = Kb[(nt * 8 + lr) * VSTR + ks * 4 + lc];
                uint32_t bfr[2] = {bb.x, bb.y};
                mma_f16(sacc[nt], a, bfr);
            }
        }

        int q0 = qt * 128 + w * 16 + lr;
        uint32_t* Ss32 = (uint32_t*)Ss;
        #pragma unroll
        for (int nt = 0; nt < 8; nt++) {
            int k0c = j * 64 + nt * 8 + 2 * lc;
            float g0 = (k0c     <= q0)     ? gelu_exact(sacc[nt][0] * 0.125f) : 0.0f;
            float g1 = (k0c + 1 <= q0)     ? gelu_exact(sacc[nt][1] * 0.125f) : 0.0f;
            float g2 = (k0c     <= q0 + 8) ? gelu_exact(sacc[nt][2] * 0.125f) : 0.0f;
            float g3 = (k0c + 1 <= q0 + 8) ? gelu_exact(sacc[nt][3] * 0.125f) : 0.0f;
            n2lo += g0 * g0 + g1 * g1;
            n2hi += g2 * g2 + g3 * g3;
            int slot = (nt >> 1) * 8 + 2 * lc + (nt & 1);
            Ss32[(w * 16 + lr)     * (2 * VSTR) + slot] = h2u(g0, g1);
            Ss32[(w * 16 + lr + 8) * (2 * VSTR) + slot] = h2u(g2, g3);
        }
        __syncwarp();

        #pragma unroll
        for (int ks = 0; ks < 4; ks++) {
            const uint2* ap = Ss + (w * 16 + lr) * VSTR + ks * 4 + lc;
            uint2 p0 = ap[0];
            uint2 p1 = ap[8 * VSTR];
            uint32_t a[4] = {p0.x, p1.x, p0.y, p1.y};
            #pragma unroll
            for (int nt = 0; nt < 8; nt++) {
                uint2 bb = Vb[(nt * 8 + lr) * VSTR + ks * 4 + lc];
                uint32_t bfr[2] = {bb.x, bb.y};
                mma_f16(oacc[nt], a, bfr);
            }
        }
        buf ^= 1;
    }

    n2lo += __shfl_xor_sync(0xffffffffu, n2lo, 1);
    n2lo += __shfl_xor_sync(0xffffffffu, n2lo, 2);
    n2hi += __shfl_xor_sync(0xffffffffu, n2hi, 1);
    n2hi += __shfl_xor_sync(0xffffffffu, n2hi, 2);

    const float sqS = 45.25483399593904f;
    float sclo = sqS * rsqrtf(n2lo);
    float schi = sqS * rsqrtf(n2hi);

    int r0 = qt * 128 + w * 16 + lr;
    #pragma unroll
    for (int nt = 0; nt < 8; nt++) {
        int c = nt * 8 + 2 * lc;
        int pp = (c & ~15) | (2 * hperm((c & 15) >> 1));
        __half* o0 = O + baseQK + (size_t)r0 * H_;
        __half* o1 = O + baseQK + (size_t)(r0 + 8) * H_;
        ((uint32_t*)o0)[pp >> 1] = h2u(oacc[nt][0] * sclo, oacc[nt][1] * sclo);
        ((uint32_t*)o1)[pp >> 1] = h2u(oacc[nt][2] * schi, oacc[nt][3] * schi);
    }
}

// ---------------- launch ----------------
extern "C" void kernel_launch(void* const* d_in, const int* in_sizes, int n_in,
                              void* d_out, int out_size) {
    const float* x        = (const float*)d_in[0];
    const float* ln1_w    = (const float*)d_in[1];
    const float* ln1_b    = (const float*)d_in[2];
    const float* ln2_w    = (const float*)d_in[3];
    const float* ln2_b    = (const float*)d_in[4];
    const float* q_key    = (const float*)d_in[5];
    const float* q_val    = (const float*)d_in[6];
    const float* k_key    = (const float*)d_in[7];
    const float* k_val    = (const float*)d_in[8];
    const float* v_key    = (const float*)d_in[9];
    const float* v_val    = (const float*)d_in[10];
    const float* proj_key = (const float*)d_in[11];
    const float* proj_val = (const float*)d_in[12];
    const float* ffn_key  = (const float*)d_in[13];
    const float* ffn_val  = (const float*)d_in[14];
    float* out = (float*)d_out;

    float *p_big, *p_x1;
    __half *p_xnh, *p_bigh, *p_oh, *p_qh, *p_kh, *p_vh, *p_vth;
    __half *p_qkh, *p_kkh, *p_vkh, *p_pkh, *p_fkh;
    __half *p_qvh, *p_kvh, *p_vvh, *p_pvh, *p_fvh;
    cudaGetSymbolAddress((void**)&p_big,  d_big);
    cudaGetSymbolAddress((void**)&p_x1,   d_x1);
    cudaGetSymbolAddress((void**)&p_xnh,  d_xnh);
    cudaGetSymbolAddress((void**)&p_bigh, d_bigh);
    cudaGetSymbolAddress((void**)&p_oh,   d_oh);
    cudaGetSymbolAddress((void**)&p_qh,   d_qh);
    cudaGetSymbolAddress((void**)&p_kh,   d_kh);
    cudaGetSymbolAddress((void**)&p_vh,   d_vh);
    cudaGetSymbolAddress((void**)&p_vth,  d_vth);
    cudaGetSymbolAddress((void**)&p_qkh,  d_qkh);
    cudaGetSymbolAddress((void**)&p_kkh,  d_kkh);
    cudaGetSymbolAddress((void**)&p_vkh,  d_vkh);
    cudaGetSymbolAddress((void**)&p_pkh,  d_pkh);
    cudaGetSymbolAddress((void**)&p_fkh,  d_fkh);
    cudaGetSymbolAddress((void**)&p_qvh,  d_qvh);
    cudaGetSymbolAddress((void**)&p_kvh,  d_kvh);
    cudaGetSymbolAddress((void**)&p_vvh,  d_vvh);
    cudaGetSymbolAddress((void**)&p_pvh,  d_pvh);
    cudaGetSymbolAddress((void**)&p_fvh,  d_fvh);

    float*  big_q = p_big;
    float*  big_k = p_big + (size_t)T_ * H_;
    float*  big_v = p_big + (size_t)2 * T_ * H_;
    __half* bgh_q = p_bigh;
    __half* bgh_k = p_bigh + (size_t)T_ * H_;
    __half* bgh_v = p_bigh + (size_t)2 * T_ * H_;

    const float sqrtH = 32.0f;
    dim3 g_small(H_ / 128, T_ / 128);
    dim3 g_small3(H_ / 128, T_ / 128, 3);
    dim3 g_ffn1(FFN_ / 128, T_ / 128);
    dim3 tthr(32, 8);

    const int smem_g = 4 * HTSZ * 8;           // 81920 bytes (2 stages x 64-k tiles)
    cudaFuncSetAttribute(hgemm_kernel<0>, cudaFuncAttributeMaxDynamicSharedMemorySize, smem_g);
    cudaFuncSetAttribute(hgemm3_kernel,   cudaFuncAttributeMaxDynamicSharedMemorySize, smem_g);
    const int smem_a = (2 * QTSZ + 4 * ATSZ) * 8;    // 81920 bytes
    cudaFuncSetAttribute(attn_kernel, cudaFuncAttributeMaxDynamicSharedMemorySize, smem_a);

    const int n16_hh = H_ * H_ / 16, n16_fh = FFN_ * H_ / 16;

    // ---- batched weight prep ----
    {
        Prep5 rp;
        rp.in[0] = q_key;  rp.out[0] = p_qkh; rp.n16[0] = n16_hh; rp.R[0] = H_;
        rp.in[1] = k_key;  rp.out[1] = p_kkh; rp.n16[1] = n16_hh; rp.R[1] = H_;
        rp.in[2] = v_key;  rp.out[2] = p_vkh; rp.n16[2] = n16_hh; rp.R[2] = H_;
        rp.in[3] = proj_key; rp.out[3] = p_pkh; rp.n16[3] = n16_hh; rp.R[3] = H_;
        rp.in[4] = ffn_key;  rp.out[4] = p_fkh; rp.n16[4] = n16_fh; rp.R[4] = FFN_;
        dim3 g((n16_fh + 255) / 256, 5);
        round_perm_kernel<<<g, 256>>>(rp);

        Prep5 tp;
        tp.in[0] = q_val;    tp.out[0] = p_qvh; tp.n16[0] = 0; tp.R[0] = H_;
        tp.in[1] = k_val;    tp.out[1] = p_kvh; tp.n16[1] = 0; tp.R[1] = H_;
        tp.in[2] = v_val;    tp.out[2] = p_vvh; tp.n16[2] = 0; tp.R[2] = H_;
        tp.in[3] = proj_val; tp.out[3] = p_pvh; tp.n16[3] = 0; tp.R[3] = H_;
        tp.in[4] = ffn_val;  tp.out[4] = p_fvh; tp.n16[4] = 0; tp.R[4] = FFN_;
        dim3 gt(H_ / 32, FFN_ / 32, 5);
        transpose_kernel<<<gt, tthr>>>(tp);
    }

    ln_kernel<<<T_, 64>>>(x, ln1_w, ln1_b, p_xnh);

    // ---- qkv pattention (batched) ----
    {
        Gemm3 g1;
        g1.A[0] = p_xnh; g1.B[0] = p_qkh; g1.C[0] = big_q; g1.emode[0] = 0;
        g1.A[1] = p_xnh; g1.B[1] = p_kkh; g1.C[1] = big_k; g1.emode[1] = 0;
        g1.A[2] = p_xnh; g1.B[2] = p_vkh; g1.C[2] = big_v; g1.emode[2] = 0;
        hgemm3_kernel<<<g_small3, 256, smem_g>>>(g1, T_, H_, H_, sqrtH);

        Rn3 rn;
        rn.in[0] = big_q; rn.out[0] = bgh_q;
        rn.in[1] = big_k; rn.out[1] = bgh_k;
        rn.in[2] = big_v; rn.out[2] = bgh_v;
        dim3 gr(T_, 3);
        rownorm3_kernel<<<gr, 64>>>(rn);

        Gemm3 g2;
        g2.A[0] = bgh_q; g2.B[0] = p_qvh; g2.C[0] = p_qh; g2.emode[0] = 1;
        g2.A[1] = bgh_k; g2.B[1] = p_kvh; g2.C[1] = p_kh; g2.emode[1] = 1;
        g2.A[2] = bgh_v; g2.B[2] = p_vvh; g2.C[2] = p_vh; g2.emode[2] = 2;
        hgemm3_kernel<<<g_small3, 256, smem_g>>>(g2, T_, H_, H_, 1.0f);
    }

    rope_kernel<<<(T_ * NH_) / 256, 256>>>(p_qh, p_kh);
    {
        dim3 vtg(S_ / 32, HD_ / 32, B_ * NH_);
        vt_kernel<<<vtg, tthr>>>(p_vh, p_vth);
    }

    {
        dim3 grid(S_ / 128, B_ * NH_);
        attn_kernel<<<grid, 256, smem_a>>>(p_qh, p_kh, p_vth, p_oh);
    }

    // proj pattention + fused residual
    hgemm_kernel<0><<<g_small, 256, smem_g>>>(p_oh, p_pkh, nullptr, big_q, T_, H_, H_, sqrtH);
    rownorm_kernel<64><<<T_, 64>>>(big_q, bgh_q, H_);
    hgemm_kernel<0><<<g_small, 256, smem_g>>>(bgh_q, p_pvh, x, p_x1, T_, H_, H_, 1.0f);

    // ffn pattention + fused residual
    ln_kernel<<<T_, 64>>>(p_x1, ln2_w, ln2_b, p_xnh);
    hgemm_kernel<0><<<g_ffn1, 256, smem_g>>>(p_xnh, p_fkh, nullptr, p_big, T_, FFN_, H_, sqrtH);
    rownorm_kernel<256><<<T_, 256>>>(p_big, p_bigh, FFN_);
    hgemm_kernel<0><<<g_small, 256, smem_g>>>(p_bigh, p_fvh, p_x1, out, T_, H_, FFN_, 1.0f);
}

// round 16
// speedup vs baseline: 1.2324x; 1.0116x over previous
#include <cuda_runtime.h>
#include <cuda_fp16.h>
#include <math.h>
#include <stdint.h>

// ---------------- problem constants ----------------
#define B_   2
#define S_   2048
#define H_   1024
#define NH_  16
#define HD_  64
#define T_   (B_*S_)      // 4096 tokens
#define FFN_ 4096
#define ROT_ 16

// ---------------- static scratch ----------------
__device__ float  d_big[T_*FFN_];
__device__ float  d_x1 [T_*H_];
__device__ __half d_xnh [T_*H_];      // ln outputs (half, plain)
__device__ __half d_bigh[T_*FFN_];    // rownorm outputs (half, plain)
__device__ __half d_oh  [T_*H_];      // attention output (half, plain)
__device__ __half d_qh  [T_*H_];      // Q (half, k-permuted; attention input)
__device__ __half d_kh  [T_*H_];      // K (half, k-permuted; attention input)
__device__ __half d_vh  [T_*H_];      // V (half, plain)
__device__ __half d_vth [T_*H_];      // V^T per head (tok-permuted; attention input)
// preprocessed weights (half, plain; vals transposed)
__device__ __half d_qkh[H_*H_];
__device__ __half d_kkh[H_*H_];
__device__ __half d_vkh[H_*H_];
__device__ __half d_pkh[H_*H_];
__device__ __half d_fkh[FFN_*H_];
__device__ __half d_qvh[H_*H_];
__device__ __half d_kvh[H_*H_];
__device__ __half d_vvh[H_*H_];
__device__ __half d_pvh[H_*H_];
__device__ __half d_fvh[H_*FFN_];

// ---------------- helpers ----------------
__device__ __forceinline__ float gelu_exact(float x) {
    return 0.5f * x * (1.0f + erff(x * 0.7071067811865475f));
}
__device__ __forceinline__ int hperm(int u) { return 2 * (u & 3) + (u >> 2); }

__device__ __forceinline__ uint32_t h2u(float a, float b) {
    __half2 h = __floats2half2_rn(a, b);
    return *(uint32_t*)&h;
}
__device__ __forceinline__ float2 u2f(uint32_t u) {
    __half2 h = *(__half2*)&u;
    return __half22float2(h);
}
// plain pack: 16 consecutive values -> 16 consecutive halves
__device__ __forceinline__ void pack16p(const float* f, uint4& lo, uint4& hi) {
    lo.x = h2u(f[0],  f[1]);  lo.y = h2u(f[2],  f[3]);
    lo.z = h2u(f[4],  f[5]);  lo.w = h2u(f[6],  f[7]);
    hi.x = h2u(f[8],  f[9]);  hi.y = h2u(f[10], f[11]);
    hi.z = h2u(f[12], f[13]); hi.w = h2u(f[14], f[15]);
}
// permuted pack (RoPE only; q/k arrays keep the attention layout)
__device__ __forceinline__ void pack16(const float* f, uint4& lo, uint4& hi) {
    lo.x = h2u(f[0], f[1]);   lo.y = h2u(f[8], f[9]);
    lo.z = h2u(f[2], f[3]);   lo.w = h2u(f[10], f[11]);
    hi.x = h2u(f[4], f[5]);   hi.y = h2u(f[12], f[13]);
    hi.z = h2u(f[6], f[7]);   hi.w = h2u(f[14], f[15]);
}
__device__ __forceinline__ void unpack16(const uint4 lo, const uint4 hi, float* f) {
    float2 t;
    t = u2f(lo.x); f[0]  = t.x; f[1]  = t.y;
    t = u2f(lo.y); f[8]  = t.x; f[9]  = t.y;
    t = u2f(lo.z); f[2]  = t.x; f[3]  = t.y;
    t = u2f(lo.w); f[10] = t.x; f[11] = t.y;
    t = u2f(hi.x); f[4]  = t.x; f[5]  = t.y;
    t = u2f(hi.y); f[12] = t.x; f[13] = t.y;
    t = u2f(hi.z); f[6]  = t.x; f[7]  = t.y;
    t = u2f(hi.w); f[14] = t.x; f[15] = t.y;
}

__device__ __forceinline__ void mma_f16(float* d, const uint32_t* a, const uint32_t* b) {
    asm volatile(
        "mma.sync.aligned.m16n8k16.row.col.f32.f16.f16.f32 "
        "{%0,%1,%2,%3}, {%4,%5,%6,%7}, {%8,%9}, {%0,%1,%2,%3};\n"
        : "+f"(d[0]), "+f"(d[1]), "+f"(d[2]), "+f"(d[3])
        : "r"(a[0]), "r"(a[1]), "r"(a[2]), "r"(a[3]), "r"(b[0]), "r"(b[1]));
}
__device__ __forceinline__ void ldsm_x4(uint32_t& r0, uint32_t& r1, uint32_t& r2, uint32_t& r3,
                                        uint32_t addr) {
    asm volatile("ldmatrix.sync.aligned.m8n8.x4.shared.b16 {%0,%1,%2,%3}, [%4];\n"
                 : "=r"(r0), "=r"(r1), "=r"(r2), "=r"(r3) : "r"(addr));
}
__device__ __forceinline__ void cp_async16(uint32_t smem_addr, const void* gptr) {
    asm volatile("cp.async.cg.shared.global [%0], [%1], 16;\n" :: "r"(smem_addr), "l"(gptr));
}
#define CP_COMMIT() asm volatile("cp.async.commit_group;\n" ::: "memory")
#define CP_WAIT(n)  asm volatile("cp.async.wait_group %0;\n" :: "n"(n) : "memory")

__device__ __forceinline__ float block_reduce_sum(float v, float* sh) {
    int lane = threadIdx.x & 31, wid = threadIdx.x >> 5;
    #pragma unroll
    for (int o = 16; o > 0; o >>= 1) v += __shfl_down_sync(0xffffffffu, v, o);
    if (lane == 0) sh[wid] = v;
    __syncthreads();
    float r = (threadIdx.x < (blockDim.x >> 5)) ? sh[threadIdx.x] : 0.0f;
    if (wid == 0) {
        #pragma unroll
        for (int o = 4; o > 0; o >>= 1) r += __shfl_down_sync(0xffffffffu, r, o);
        if (lane == 0) sh[0] = r;
    }
    __syncthreads();
    r = sh[0];
    __syncthreads();
    return r;
}

// ---------------- batched param structs ----------------
struct Prep5 {
    const float* in[5];
    __half* out[5];
    int n16[5];
    int R[5];
};
struct Gemm3 {
    const __half* A[3];
    const __half* B[3];
    void* C[3];
    int emode[3];
};
struct Rn3 {
    const float* in[3];
    __half* out[3];
};

// ---------------- batched weight prep: fp32 -> half (plain) ----------------
__global__ void round_perm_kernel(Prep5 p) {
    int z = blockIdx.y;
    int i = blockIdx.x * blockDim.x + threadIdx.x;
    if (i >= p.n16[z]) return;
    const float* src = p.in[z] + (size_t)i * 16;
    float f[16];
    #pragma unroll
    for (int j = 0; j < 16; j += 4) {
        float4 v = *(const float4*)(src + j);
        f[j] = v.x; f[j+1] = v.y; f[j+2] = v.z; f[j+3] = v.w;
    }
    uint4 lo, hi;
    pack16p(f, lo, hi);
    uint4* o = (uint4*)(p.out[z] + (size_t)i * 16);
    o[0] = lo; o[1] = hi;
}

// ---------------- batched transpose + half (plain) ----------------
__global__ void transpose_kernel(Prep5 p) {
    __shared__ float t[32][33];
    int z = blockIdx.z;
    int R = p.R[z];
    if (blockIdx.y * 32 >= R) return;
    const float* in = p.in[z];
    __half* out = p.out[z];
    int x  = blockIdx.x * 32 + threadIdx.x;
    int y0 = blockIdx.y * 32;
    #pragma unroll
    for (int i = threadIdx.y; i < 32; i += 8)
        t[i][threadIdx.x] = in[(size_t)(y0 + i) * H_ + x];
    __syncthreads();
    int xo = blockIdx.y * 32 + threadIdx.x;
    int yo0 = blockIdx.x * 32;
    #pragma unroll
    for (int i = threadIdx.y; i < 32; i += 8)
        out[(size_t)(yo0 + i) * R + xo] = __float2half(t[threadIdx.x][i]);
}

// ---------------- V^T per head (tok-permuted; attention consumes) ----------------
__global__ void vt_kernel(const __half* __restrict__ V, __half* __restrict__ VT) {
    __shared__ __half t[32][34];
    int bh   = blockIdx.z;
    int b    = bh >> 4, h = bh & 15;
    int tok0 = blockIdx.x * 32;
    int dim0 = blockIdx.y * 32;
    int tx = threadIdx.x, ty = threadIdx.y;
    #pragma unroll
    for (int i = ty; i < 32; i += 8)
        t[i][tx] = V[(size_t)(b * S_ + tok0 + i) * H_ + h * HD_ + dim0 + tx];
    __syncthreads();
    int tok = tok0 + tx;
    int tokp = (tok & ~15) | (2 * hperm((tok & 15) >> 1) + (tok & 1));
    #pragma unroll
    for (int i = ty; i < 32; i += 8)
        VT[(size_t)(bh * HD_ + dim0 + i) * S_ + tokp] = t[tx][i];
}

// ---------------- LayerNorm: fp32 -> half plain ----------------
__global__ void ln_kernel(const float* __restrict__ x, const float* __restrict__ w,
                          const float* __restrict__ b, __half* __restrict__ y) {
    __shared__ float sh[32];
    int row = blockIdx.x;
    int tid = threadIdx.x;
    const float* xr = x + (size_t)row * H_ + tid * 16;
    float f[16];
    float s = 0.0f, sq = 0.0f;
    #pragma unroll
    for (int j = 0; j < 16; j += 4) {
        float4 v = *(const float4*)(xr + j);
        f[j] = v.x; f[j+1] = v.y; f[j+2] = v.z; f[j+3] = v.w;
        s  += v.x + v.y + v.z + v.w;
        sq += v.x*v.x + v.y*v.y + v.z*v.z + v.w*v.w;
    }
    float S  = block_reduce_sum(s,  sh);
    float SQ = block_reduce_sum(sq, sh);
    float mu  = S * (1.0f / H_);
    float var = SQ * (1.0f / H_) - mu * mu;
    float inv = rsqrtf(var + 1e-5f);
    const float* wr = w + tid * 16;
    const float* br = b + tid * 16;
    #pragma unroll
    for (int j = 0; j < 16; j++)
        f[j] = (f[j] - mu) * inv * wr[j] + br[j];
    uint4 lo, hi;
    pack16p(f, lo, hi);
    uint4* o = (uint4*)(y + (size_t)row * H_ + tid * 16);
    o[0] = lo; o[1] = hi;
}

// ---------------- gelu + L2-rownorm -> half plain ----------------
__device__ __forceinline__ void rownorm_row(const float* ar, __half* orow, int cols, float* sh) {
    int tid = threadIdx.x;
    const float* src = ar + tid * 16;
    float g[16];
    float s = 0.0f;
    #pragma unroll
    for (int j = 0; j < 16; j += 4) {
        float4 v = *(const float4*)(src + j);
        g[j]   = gelu_exact(v.x); g[j+1] = gelu_exact(v.y);
        g[j+2] = gelu_exact(v.z); g[j+3] = gelu_exact(v.w);
        s += g[j]*g[j] + g[j+1]*g[j+1] + g[j+2]*g[j+2] + g[j+3]*g[j+3];
    }
    float tot = block_reduce_sum(s, sh);
    float sc = sqrtf((float)cols) * rsqrtf(tot);
    #pragma unroll
    for (int j = 0; j < 16; j++) g[j] *= sc;
    uint4 lo, hi;
    pack16p(g, lo, hi);
    uint4* o = (uint4*)(orow + tid * 16);
    o[0] = lo; o[1] = hi;
}

__global__ void rownorm3_kernel(Rn3 p) {
    __shared__ float sh[32];
    int z = blockIdx.y, row = blockIdx.x;
    rownorm_row(p.in[z] + (size_t)row * H_, p.out[z] + (size_t)row * H_, H_, sh);
}
template <int NT>
__global__ void rownorm_kernel(const float* __restrict__ in, __half* __restrict__ out, int cols) {
    __shared__ float sh[32];
    int row = blockIdx.x;
    rownorm_row(in + (size_t)row * cols, out + (size_t)row * cols, cols, sh);
}

// ---------------- FP16 GEMM (NT, 128x128x64 k-tile, cp.async 2-stage, ldmatrix) --------------
// Plain k-contiguous smem rows; row stride 144B (36 uints) -> ldmatrix conflict-free.
#define HSTR2 18                   // uint2 per row
#define HTSZ  (128 * HSTR2)        // uint2 per tile buffer
#define HROWB 144                  // row bytes

__device__ __forceinline__ void hgemm_body(
    const __half* A, const __half* Bm, const float* Res, void* Cv,
    int M, int N, int K, float alpha, int emode, uint2* sh2)
{
    uint2* As = sh2;              // [2][HTSZ]
    uint2* Bs = sh2 + 2 * HTSZ;   // [2][HTSZ]

    const int bx = blockIdx.x, by = blockIdx.y;
    const int tid = threadIdx.x;
    const int lane = tid & 31, w = tid >> 5;
    const int wm = w & 3, wn = w >> 2;          // 4x2 warps; warp tile 32m x 64n
    const int lr = lane >> 2, lc = lane & 3;

    float acc[2][8][4];
    #pragma unroll
    for (int i = 0; i < 2; i++)
        #pragma unroll
        for (int j = 0; j < 8; j++)
            #pragma unroll
            for (int t = 0; t < 4; t++) acc[i][j][t] = 0.0f;

    const int iters = K >> 6;                   // 64-k tiles

    auto load_tile = [&](int t, int buf) {
        int k0 = t << 6;
        #pragma unroll
        for (int it = 0; it < 4; it++) {
            int slot = tid + it * 256;
            int r = slot >> 3, off = slot & 7;
            const __half* srcA = A + (size_t)(by * 128 + r) * K + k0 + off * 8;
            uint32_t dA = (uint32_t)__cvta_generic_to_shared(As + buf * HTSZ + r * HSTR2 + off * 2);
            cp_async16(dA, srcA);
            const __half* srcB = Bm + (size_t)(bx * 128 + r) * K + k0 + off * 8;
            uint32_t dB = (uint32_t)__cvta_generic_to_shared(Bs + buf * HTSZ + r * HSTR2 + off * 2);
            cp_async16(dB, srcB);
        }
    };

    load_tile(0, 0);
    CP_COMMIT();

    // ldmatrix lane addresses: lane = 8*j + r; matrix j: (j&1)->m8 row group, (j>>1)->k8 chunk
    const int jm = lane >> 3, rr = lane & 7;
    const uint32_t aLaneOff = (uint32_t)((wm * 32 + (jm & 1) * 8 + rr) * HROWB + (jm >> 1) * 16);
    const uint32_t bLaneOff = (uint32_t)((wn * 64 + (jm & 1) * 8 + rr) * HROWB + (jm >> 1) * 16);
    const uint32_t sA = (uint32_t)__cvta_generic_to_shared(As);
    const uint32_t sB = (uint32_t)__cvta_generic_to_shared(Bs);

    int buf = 0;
    for (int t = 0; t < iters; t++) {
        CP_WAIT(0);
        __syncthreads();
        if (t + 1 < iters) {
            load_tile(t + 1, buf ^ 1);
            CP_COMMIT();
        }
        uint32_t aAddr = sA + (uint32_t)(buf * HTSZ * 8) + aLaneOff;
        uint32_t bAddr = sB + (uint32_t)(buf * HTSZ * 8) + bLaneOff;
        #pragma unroll
        for (int ks = 0; ks < 4; ks++) {        // four k16 steps; chunk offset ks*32B
            uint32_t afr[2][4];
            ldsm_x4(afr[0][0], afr[0][1], afr[0][2], afr[0][3], aAddr + ks * 32);
            ldsm_x4(afr[1][0], afr[1][1], afr[1][2], afr[1][3], aAddr + 16 * HROWB + ks * 32);
            #pragma unroll
            for (int p = 0; p < 4; p++) {
                uint32_t b0, b1, b2, b3;
                ldsm_x4(b0, b1, b2, b3, bAddr + p * 16 * HROWB + ks * 32);
                uint32_t bf0[2] = {b0, b2};
                uint32_t bf1[2] = {b1, b3};
                mma_f16(acc[0][2 * p],     afr[0], bf0);
                mma_f16(acc[0][2 * p + 1], afr[0], bf1);
                mma_f16(acc[1][2 * p],     afr[1], bf0);
                mma_f16(acc[1][2 * p + 1], afr[1], bf1);
            }
        }
        buf ^= 1;
    }

    #pragma unroll
    for (int mt = 0; mt < 2; mt++) {
        int r0 = by * 128 + wm * 32 + mt * 16 + lr;
        #pragma unroll
        for (int nt = 0; nt < 8; nt++) {
            int c = bx * 128 + wn * 64 + nt * 8 + 2 * lc;
            float a0 = acc[mt][nt][0] * alpha, a1 = acc[mt][nt][1] * alpha;
            float a2 = acc[mt][nt][2] * alpha, a3 = acc[mt][nt][3] * alpha;
            if (emode == 0) {
                float* C = (float*)Cv;
                float2 lo = {a0, a1}, hi = {a2, a3};
                if (Res) {
                    float2 rlo = *(const float2*)(Res + (size_t)r0 * N + c);
                    float2 rhi = *(const float2*)(Res + (size_t)(r0 + 8) * N + c);
                    lo.x += rlo.x; lo.y += rlo.y; hi.x += rhi.x; hi.y += rhi.y;
                }
                *(float2*)(C + (size_t)r0 * N + c)       = lo;
                *(float2*)(C + (size_t)(r0 + 8) * N + c) = hi;
            } else if (emode == 1) {
                // half, k-pair-permuted output (feeds attention Q/K path)
                __half* C = (__half*)Cv;
                int hoff = (c & ~15) + 4 * lc + 2 * (nt & 1);
                ((uint32_t*)(C + (size_t)r0 * N))[hoff >> 1]       = h2u(a0, a1);
                ((uint32_t*)(C + (size_t)(r0 + 8) * N))[hoff >> 1] = h2u(a2, a3);
            } else {
                __half* C = (__half*)Cv;
                ((uint32_t*)(C + (size_t)r0 * N))[c >> 1]       = h2u(a0, a1);
                ((uint32_t*)(C + (size_t)(r0 + 8) * N))[c >> 1] = h2u(a2, a3);
            }
        }
    }
}

template <int EMODE>
__global__ void __launch_bounds__(256, 2) hgemm_kernel(
    const __half* __restrict__ A, const __half* __restrict__ Bm,
    const float* __restrict__ Res, void* __restrict__ Cv,
    int M, int N, int K, float alpha)
{
    extern __shared__ uint2 sh2[];
    hgemm_body(A, Bm, Res, Cv, M, N, K, alpha, EMODE, sh2);
}

__global__ void __launch_bounds__(256, 2) hgemm3_kernel(
    Gemm3 g, int M, int N, int K, float alpha)
{
    extern __shared__ uint2 sh2[];
    int z = blockIdx.z;
    hgemm_body(g.A[z], g.B[z], nullptr, g.C[z], M, N, K, alpha, g.emode[z], sh2);
}

// ---------------- RoPE on half k-permuted Q,K ----------------
__global__ void rope_kernel(__half* __restrict__ q, __half* __restrict__ k) {
    int idx = blockIdx.x * blockDim.x + threadIdx.x;
    if (idx >= T_ * NH_) return;
    int h  = idx & (NH_ - 1);
    int bs = idx >> 4;
    int s  = bs & (S_ - 1);
    __half* qp = q + (size_t)bs * H_ + h * HD_;
    __half* kp = k + (size_t)bs * H_ + h * HD_;
    uint4 qlo = *(uint4*)qp, qhi = *(uint4*)(qp + 8);
    uint4 klo = *(uint4*)kp, khi = *(uint4*)(kp + 8);
    float qv[16], kv[16];
    unpack16(qlo, qhi, qv);
    unpack16(klo, khi, kv);
    #pragma unroll
    for (int i = 0; i < ROT_ / 2; i++) {
        double invf = pow(10000.0, -(double)(2 * i) / (double)ROT_);
        double ang = (double)s * invf;
        float c  = (float)cos(ang);
        float sn = (float)sin(ang);
        float q0 = qv[i], q1 = qv[i + 8];
        qv[i]     = q0 * c - q1 * sn;
        qv[i + 8] = q1 * c + q0 * sn;
        float k0 = kv[i], k1 = kv[i + 8];
        kv[i]     = k0 * c - k1 * sn;
        kv[i + 8] = k1 * c + k0 * sn;
    }
    pack16(qv, qlo, qhi);
    pack16(kv, klo, khi);
    *(uint4*)qp = qlo; *(uint4*)(qp + 8) = qhi;
    *(uint4*)kp = klo; *(uint4*)(kp + 8) = khi;
}

// ---------------- fused causal attention (fp16 mma, 128-q tiles, 8 warps) ----------------
#define VSTR 20
#define ATSZ (64 * VSTR)
#define QTSZ (128 * VSTR)

__global__ void __launch_bounds__(256, 2) attn_kernel(
    const __half* __restrict__ Q, const __half* __restrict__ K,
    const __half* __restrict__ VT, __half* __restrict__ O)
{
    extern __shared__ uint2 sm2[];
    uint2* Qs = sm2;
    uint2* Ks = Qs + QTSZ;
    uint2* Vs = Ks + 2 * ATSZ;
    uint2* Ss = Vs + 2 * ATSZ;

    const int qt  = blockIdx.x;
    const int bh  = blockIdx.y;
    const int b   = bh >> 4, h = bh & 15;
    const int tid = threadIdx.x;
    const int lane = tid & 31, w = tid >> 5;
    const int lr = lane >> 2, lc = lane & 3;
    const size_t baseQK = (size_t)(b * S_) * H_ + h * HD_;
    const size_t baseVT = (size_t)(bh * HD_) * S_;

    #pragma unroll
    for (int it = 0; it < 4; it++) {
        int c = tid + it * 256;
        int r = c >> 3, off = c & 7;
        const __half* src = Q + baseQK + (size_t)(qt * 128 + r) * H_ + off * 8;
        uint32_t dst = (uint32_t)__cvta_generic_to_shared(Qs + r * VSTR + off * 2);
        cp_async16(dst, src);
    }
    #pragma unroll
    for (int it = 0; it < 2; it++) {
        int c = tid + it * 256;
        int r = c >> 3, off = c & 7;
        const __half* srck = K + baseQK + (size_t)r * H_ + off * 8;
        uint32_t dk = (uint32_t)__cvta_generic_to_shared(Ks + r * VSTR + off * 2);
        cp_async16(dk, srck);
        const __half* srcv = VT + baseVT + (size_t)r * S_ + off * 8;
        uint32_t dv = (uint32_t)__cvta_generic_to_shared(Vs + r * VSTR + off * 2);
        cp_async16(dv, srcv);
    }
    CP_COMMIT();

    float oacc[8][4];
    #pragma unroll
    for (int i = 0; i < 8; i++)
        #pragma unroll
        for (int j = 0; j < 4; j++) oacc[i][j] = 0.0f;
    float n2lo = 0.0f, n2hi = 0.0f;

    const int jmax = 2 * qt + 1;
    int buf = 0;
    for (int j = 0; j <= jmax; j++) {
        CP_WAIT(0);
        __syncthreads();

        if (j < jmax) {
            #pragma unroll
            for (int it = 0; it < 2; it++) {
                int c = tid + it * 256;
                int r = c >> 3, off = c & 7;
                const __half* srck = K + baseQK + (size_t)((j + 1) * 64 + r) * H_ + off * 8;
                uint32_t dk = (uint32_t)__cvta_generic_to_shared(Ks + (buf ^ 1) * ATSZ + r * VSTR + off * 2);
                cp_async16(dk, srck);
                const __half* srcv = VT + baseVT + (size_t)r * S_ + (j + 1) * 64 + off * 8;
                uint32_t dv = (uint32_t)__cvta_generic_to_shared(Vs + (buf ^ 1) * ATSZ + r * VSTR + off * 2);
                cp_async16(dv, srcv);
            }
            CP_COMMIT();
        }

        const uint2* Kb = Ks + buf * ATSZ;
        const uint2* Vb = Vs + buf * ATSZ;

        float sacc[8][4];
        #pragma unroll
        for (int i = 0; i < 8; i++)
            #pragma unroll
            for (int jj = 0; jj < 4; jj++) sacc[i][jj] = 0.0f;
        #pragma unroll
        for (int ks = 0; ks < 4; ks++) {
            const uint2* ap = Qs + (w * 16 + lr) * VSTR + ks * 4 + lc;
            uint2 p0 = ap[0];
            uint2 p1 = ap[8 * VSTR];
            uint32_t a[4] = {p0.x, p1.x, p0.y, p1.y};
            #pragma unroll
            for (int nt = 0; nt < 8; nt++) {
                uint2 bb = Kb[(nt * 8 + lr) * VSTR + ks * 4 + lc];
                uint32_t bfr[2] = {bb.x, bb.y};
                mma_f16(sacc[nt], a, bfr);
            }
        }

        int q0 = qt * 128 + w * 16 + lr;
        uint32_t* Ss32 = (uint32_t*)Ss;
        #pragma unroll
        for (int nt = 0; nt < 8; nt++) {
            int k0c = j * 64 + nt * 8 + 2 * lc;
            float g0 = (k0c     <= q0)     ? gelu_exact(sacc[nt][0] * 0.125f) : 0.0f;
            float g1 = (k0c + 1 <= q0)     ? gelu_exact(sacc[nt][1] * 0.125f) : 0.0f;
            float g2 = (k0c     <= q0 + 8) ? gelu_exact(sacc[nt][2] * 0.125f) : 0.0f;
            float g3 = (k0c + 1 <= q0 + 8) ? gelu_exact(sacc[nt][3] * 0.125f) : 0.0f;
            n2lo += g0 * g0 + g1 * g1;
            n2hi += g2 * g2 + g3 * g3;
            int slot = (nt >> 1) * 8 + 2 * lc + (nt & 1);
            Ss32[(w * 16 + lr)     * (2 * VSTR) + slot] = h2u(g0, g1);
            Ss32[(w * 16 + lr + 8) * (2 * VSTR) + slot] = h2u(g2, g3);
        }
        __syncwarp();

        #pragma unroll
        for (int ks = 0; ks < 4; ks++) {
            const uint2* ap = Ss + (w * 16 + lr) * VSTR + ks * 4 + lc;
            uint2 p0 = ap[0];
            uint2 p1 = ap[8 * VSTR];
            uint32_t a[4] = {p0.x, p1.x, p0.y, p1.y};
            #pragma unroll
            for (int nt = 0; nt < 8; nt++) {
                uint2 bb = Vb[(nt * 8 + lr) * VSTR + ks * 4 + lc];
                uint32_t bfr[2] = {bb.x, bb.y};
                mma_f16(oacc[nt], a, bfr);
            }
        }
        buf ^= 1;
    }

    n2lo += __shfl_xor_sync(0xffffffffu, n2lo, 1);
    n2lo += __shfl_xor_sync(0xffffffffu, n2lo, 2);
    n2hi += __shfl_xor_sync(0xffffffffu, n2hi, 1);
    n2hi += __shfl_xor_sync(0xffffffffu, n2hi, 2);

    const float sqS = 45.25483399593904f;
    float sclo = sqS * rsqrtf(n2lo);
    float schi = sqS * rsqrtf(n2hi);

    // store half, PLAIN (feeds proj GEMM via ldmatrix)
    int r0 = qt * 128 + w * 16 + lr;
    #pragma unroll
    for (int nt = 0; nt < 8; nt++) {
        int c = nt * 8 + 2 * lc;
        __half* o0 = O + baseQK + (size_t)r0 * H_;
        __half* o1 = O + baseQK + (size_t)(r0 + 8) * H_;
        ((uint32_t*)o0)[c >> 1] = h2u(oacc[nt][0] * sclo, oacc[nt][1] * sclo);
        ((uint32_t*)o1)[c >> 1] = h2u(oacc[nt][2] * schi, oacc[nt][3] * schi);
    }
}

// ---------------- launch ----------------
extern "C" void kernel_launch(void* const* d_in, const int* in_sizes, int n_in,
                              void* d_out, int out_size) {
    const float* x        = (const float*)d_in[0];
    const float* ln1_w    = (const float*)d_in[1];
    const float* ln1_b    = (const float*)d_in[2];
    const float* ln2_w    = (const float*)d_in[3];
    const float* ln2_b    = (const float*)d_in[4];
    const float* q_key    = (const float*)d_in[5];
    const float* q_val    = (const float*)d_in[6];
    const float* k_key    = (const float*)d_in[7];
    const float* k_val    = (const float*)d_in[8];
    const float* v_key    = (const float*)d_in[9];
    const float* v_val    = (const float*)d_in[10];
    const float* proj_key = (const float*)d_in[11];
    const float* proj_val = (const float*)d_in[12];
    const float* ffn_key  = (const float*)d_in[13];
    const float* ffn_val  = (const float*)d_in[14];
    float* out = (float*)d_out;

    float *p_big, *p_x1;
    __half *p_xnh, *p_bigh, *p_oh, *p_qh, *p_kh, *p_vh, *p_vth;
    __half *p_qkh, *p_kkh, *p_vkh, *p_pkh, *p_fkh;
    __half *p_qvh, *p_kvh, *p_vvh, *p_pvh, *p_fvh;
    cudaGetSymbolAddress((void**)&p_big,  d_big);
    cudaGetSymbolAddress((void**)&p_x1,   d_x1);
    cudaGetSymbolAddress((void**)&p_xnh,  d_xnh);
    cudaGetSymbolAddress((void**)&p_bigh, d_bigh);
    cudaGetSymbolAddress((void**)&p_oh,   d_oh);
    cudaGetSymbolAddress((void**)&p_qh,   d_qh);
    cudaGetSymbolAddress((void**)&p_kh,   d_kh);
    cudaGetSymbolAddress((void**)&p_vh,   d_vh);
    cudaGetSymbolAddress((void**)&p_vth,  d_vth);
    cudaGetSymbolAddress((void**)&p_qkh,  d_qkh);
    cudaGetSymbolAddress((void**)&p_kkh,  d_kkh);
    cudaGetSymbolAddress((void**)&p_vkh,  d_vkh);
    cudaGetSymbolAddress((void**)&p_pkh,  d_pkh);
    cudaGetSymbolAddress((void**)&p_fkh,  d_fkh);
    cudaGetSymbolAddress((void**)&p_qvh,  d_qvh);
    cudaGetSymbolAddress((void**)&p_kvh,  d_kvh);
    cudaGetSymbolAddress((void**)&p_vvh,  d_vvh);
    cudaGetSymbolAddress((void**)&p_pvh,  d_pvh);
    cudaGetSymbolAddress((void**)&p_fvh,  d_fvh);

    float*  big_q = p_big;
    float*  big_k = p_big + (size_t)T_ * H_;
    float*  big_v = p_big + (size_t)2 * T_ * H_;
    __half* bgh_q = p_bigh;
    __half* bgh_k = p_bigh + (size_t)T_ * H_;
    __half* bgh_v = p_bigh + (size_t)2 * T_ * H_;

    const float sqrtH = 32.0f;
    dim3 g_small(H_ / 128, T_ / 128);
    dim3 g_small3(H_ / 128, T_ / 128, 3);
    dim3 g_ffn1(FFN_ / 128, T_ / 128);
    dim3 tthr(32, 8);

    const int smem_g = 4 * HTSZ * 8;           // 73728 bytes
    cudaFuncSetAttribute(hgemm_kernel<0>, cudaFuncAttributeMaxDynamicSharedMemorySize, smem_g);
    cudaFuncSetAttribute(hgemm3_kernel,   cudaFuncAttributeMaxDynamicSharedMemorySize, smem_g);
    const int smem_a = (2 * QTSZ + 4 * ATSZ) * 8;    // 81920 bytes
    cudaFuncSetAttribute(attn_kernel, cudaFuncAttributeMaxDynamicSharedMemorySize, smem_a);

    const int n16_hh = H_ * H_ / 16, n16_fh = FFN_ * H_ / 16;

    // ---- batched weight prep ----
    {
        Prep5 rp;
        rp.in[0] = q_key;  rp.out[0] = p_qkh; rp.n16[0] = n16_hh; rp.R[0] = H_;
        rp.in[1] = k_key;  rp.out[1] = p_kkh; rp.n16[1] = n16_hh; rp.R[1] = H_;
        rp.in[2] = v_key;  rp.out[2] = p_vkh; rp.n16[2] = n16_hh; rp.R[2] = H_;
        rp.in[3] = proj_key; rp.out[3] = p_pkh; rp.n16[3] = n16_hh; rp.R[3] = H_;
        rp.in[4] = ffn_key;  rp.out[4] = p_fkh; rp.n16[4] = n16_fh; rp.R[4] = FFN_;
        dim3 g((n16_fh + 255) / 256, 5);
        round_perm_kernel<<<g, 256>>>(rp);

        Prep5 tp;
        tp.in[0] = q_val;    tp.out[0] = p_qvh; tp.n16[0] = 0; tp.R[0] = H_;
        tp.in[1] = k_val;    tp.out[1] = p_kvh; tp.n16[1] = 0; tp.R[1] = H_;
        tp.in[2] = v_val;    tp.out[2] = p_vvh; tp.n16[2] = 0; tp.R[2] = H_;
        tp.in[3] = proj_val; tp.out[3] = p_pvh; tp.n16[3] = 0; tp.R[3] = H_;
        tp.in[4] = ffn_val;  tp.out[4] = p_fvh; tp.n16[4] = 0; tp.R[4] = FFN_;
        dim3 gt(H_ / 32, FFN_ / 32, 5);
        transpose_kernel<<<gt, tthr>>>(tp);
    }

    ln_kernel<<<T_, 64>>>(x, ln1_w, ln1_b, p_xnh);

    // ---- qkv pattention (batched) ----
    {
        Gemm3 g1;
        g1.A[0] = p_xnh; g1.B[0] = p_qkh; g1.C[0] = big_q; g1.emode[0] = 0;
        g1.A[1] = p_xnh; g1.B[1] = p_kkh; g1.C[1] = big_k; g1.emode[1] = 0;
        g1.A[2] = p_xnh; g1.B[2] = p_vkh; g1.C[2] = big_v; g1.emode[2] = 0;
        hgemm3_kernel<<<g_small3, 256, smem_g>>>(g1, T_, H_, H_, sqrtH);

        Rn3 rn;
        rn.in[0] = big_q; rn.out[0] = bgh_q;
        rn.in[1] = big_k; rn.out[1] = bgh_k;
        rn.in[2] = big_v; rn.out[2] = bgh_v;
        dim3 gr(T_, 3);
        rownorm3_kernel<<<gr, 64>>>(rn);

        Gemm3 g2;
        g2.A[0] = bgh_q; g2.B[0] = p_qvh; g2.C[0] = p_qh; g2.emode[0] = 1;
        g2.A[1] = bgh_k; g2.B[1] = p_kvh; g2.C[1] = p_kh; g2.emode[1] = 1;
        g2.A[2] = bgh_v; g2.B[2] = p_vvh; g2.C[2] = p_vh; g2.emode[2] = 2;
        hgemm3_kernel<<<g_small3, 256, smem_g>>>(g2, T_, H_, H_, 1.0f);
    }

    rope_kernel<<<(T_ * NH_) / 256, 256>>>(p_qh, p_kh);
    {
        dim3 vtg(S_ / 32, HD_ / 32, B_ * NH_);
        vt_kernel<<<vtg, tthr>>>(p_vh, p_vth);
    }

    {
        dim3 grid(S_ / 128, B_ * NH_);
        attn_kernel<<<grid, 256, smem_a>>>(p_qh, p_kh, p_vth, p_oh);
    }

    // proj pattention + fused residual
    hgemm_kernel<0><<<g_small, 256, smem_g>>>(p_oh, p_pkh, nullptr, big_q, T_, H_, H_, sqrtH);
    rownorm_kernel<64><<<T_, 64>>>(big_q, bgh_q, H_);
    hgemm_kernel<0><<<g_small, 256, smem_g>>>(bgh_q, p_pvh, x, p_x1, T_, H_, H_, 1.0f);

    // ffn pattention + fused residual
    ln_kernel<<<T_, 64>>>(p_x1, ln2_w, ln2_b, p_xnh);
    hgemm_kernel<0><<<g_ffn1, 256, smem_g>>>(p_xnh, p_fkh, nullptr, p_big, T_, FFN_, H_, sqrtH);
    rownorm_kernel<256><<<T_, 256>>>(p_big, p_bigh, FFN_);
    hgemm_kernel<0><<<g_small, 256, smem_g>>>(p_bigh, p_fvh, p_x1, out, T_, H_, FFN_, 1.0f);
}